// round 3
// baseline (speedup 1.0000x reference)
#include <cuda_runtime.h>
#include <math.h>

#define VSZ  32000
#define EDIM 256
#define DDIM 512
#define BDIM 32
#define TDIM 128
#define SDIM 128
#define PADI 3
#define G4D  2048

// ------------- static device scratch (no runtime allocation) -------------
__device__ float g_X0[(size_t)TDIM * BDIM * G4D];          // 33.5 MB
__device__ float g_A [(size_t)BDIM * TDIM * 2 * DDIM];     // 16.8 MB, row = b*T+t
__device__ float g_s0[2][BDIM * DDIM];
__device__ float g_s1[2][BDIM * DDIM];
__device__ float g_c0[BDIM * DDIM];
__device__ float g_c1[BDIM * DDIM];

__device__ __forceinline__ float sigf(float x){ return 1.0f / (1.0f + expf(-x)); }

// ------------- packed f32x2 helpers -------------
__device__ __forceinline__ unsigned long long splat2(float x){
    unsigned long long u; unsigned r = __float_as_uint(x);
    asm("mov.b64 %0, {%1, %1};" : "=l"(u) : "r"(r));
    return u;
}
__device__ __forceinline__ void ffma2(unsigned long long& d, unsigned long long a, unsigned long long b){
    asm("fma.rn.f32x2 %0, %1, %2, %3;" : "=l"(d) : "l"(a), "l"(b), "l"(d));
}
__device__ __forceinline__ unsigned long long add2(unsigned long long a, unsigned long long b){
    unsigned long long d;
    asm("add.rn.f32x2 %0, %1, %2;" : "=l"(d) : "l"(a), "l"(b));
    return d;
}

// ------------- init recurrent state -------------
__global__ void k_init(const float* __restrict__ s0, const float* __restrict__ c0){
    int i = blockIdx.x * 256 + threadIdx.x;
    if (i < BDIM * DDIM){
        g_s0[0][i] = s0[i];
        g_s1[0][i] = s0[BDIM * DDIM + i];
        g_c0[i]    = c0[i];
        g_c1[i]    = c0[BDIM * DDIM + i];
    }
}

// ------------- X0 = emb_eff[tok] @ Wih0^T + bih0 + bhh0 -------------
// M=4096 (row m = t*B + b), N=2048, K=256. 64x64 tile, 256 thr, 4x4/thread.
__global__ void k_x0(const int* __restrict__ tar, const float* __restrict__ emb,
                     const float* __restrict__ W, const float* __restrict__ b1,
                     const float* __restrict__ b2){
    __shared__ __align__(16) float Ast[32][68];
    __shared__ __align__(16) float Bst[32][68];
    const int tid = threadIdx.x;
    const int n0 = blockIdx.x * 64, m0 = blockIdx.y * 64;
    const int mg = tid >> 4, ng = tid & 15;
    const int ml0 = mg * 4, nl0 = ng * 4;
    const int kl = tid & 31, rl = tid >> 5;
    float acc[4][4] = {};
    for (int kc = 0; kc < EDIM; kc += 32){
        #pragma unroll
        for (int l = 0; l < 8; l++){
            int ml = rl + l * 8;
            int m  = m0 + ml;
            int tt = m >> 5, bb = m & 31;
            int tok = tar[bb * TDIM + tt];
            Ast[kl][ml] = (tok == PADI) ? 0.0f : emb[tok * EDIM + kc + kl];
            int nl = rl + l * 8;
            Bst[kl][nl] = W[(n0 + nl) * EDIM + kc + kl];
        }
        __syncthreads();
        #pragma unroll 8
        for (int k = 0; k < 32; k++){
            float ra[4], rb[4];
            #pragma unroll
            for (int i = 0; i < 4; i++) ra[i] = Ast[k][ml0 + i];
            #pragma unroll
            for (int j = 0; j < 4; j++) rb[j] = Bst[k][nl0 + j];
            #pragma unroll
            for (int i = 0; i < 4; i++)
                #pragma unroll
                for (int j = 0; j < 4; j++) acc[i][j] += ra[i] * rb[j];
        }
        __syncthreads();
    }
    #pragma unroll
    for (int i = 0; i < 4; i++){
        int m = m0 + ml0 + i;
        #pragma unroll
        for (int j = 0; j < 4; j++){
            int n = n0 + nl0 + j;
            g_X0[(size_t)m * G4D + n] = acc[i][j] + b1[n] + b2[n];
        }
    }
}

// ------------- LSTM cell, layer 0 -------------
// 64 blocks (8 d each -> 32 gate rows), 64 threads, 4r x 4b per thread, K=512.
// gates = X0[t] (x-part + both biases) + s0_prev @ Whh0^T; fused pointwise.
__global__ void k_cell0(int t, const float* __restrict__ Whh){
    __shared__ __align__(16) float St[64][36];   // [k][b]
    __shared__ __align__(16) float Wt[64][36];   // [k][lr]
    __shared__ float gsm[32][33];                // [lr][b]
    const int tid = threadIdx.x;                 // 64
    const int d0 = blockIdx.x * 8;
    const int ping = t & 1;
    const float* S = g_s0[ping];
    const int rg = tid >> 3, bg = tid & 7;
    const int lr0 = rg * 4, b0 = bg * 4;
    float acc[4][4] = {};
    for (int kc = 0; kc < DDIM; kc += 64){
        #pragma unroll 4
        for (int l = 0; l < 32; l++){
            St[tid][l] = S[l * DDIM + kc + tid];
            int r = (l >> 3) * DDIM + d0 + (l & 7);
            Wt[tid][l] = Whh[r * DDIM + kc + tid];
        }
        __syncthreads();
        #pragma unroll 8
        for (int k = 0; k < 64; k++){
            float rw[4], rs[4];
            #pragma unroll
            for (int i = 0; i < 4; i++) rw[i] = Wt[k][lr0 + i];
            #pragma unroll
            for (int j = 0; j < 4; j++) rs[j] = St[k][b0 + j];
            #pragma unroll
            for (int i = 0; i < 4; i++)
                #pragma unroll
                for (int j = 0; j < 4; j++) acc[i][j] += rw[i] * rs[j];
        }
        __syncthreads();
    }
    const float* pre = g_X0 + (size_t)t * BDIM * G4D;
    #pragma unroll
    for (int i = 0; i < 4; i++){
        int lr = lr0 + i;
        int r  = (lr >> 3) * DDIM + d0 + (lr & 7);
        #pragma unroll
        for (int j = 0; j < 4; j++){
            int bb = b0 + j;
            gsm[lr][bb] = acc[i][j] + pre[bb * G4D + r];
        }
    }
    __syncthreads();
    float* sout = g_s0[ping ^ 1];
    #pragma unroll
    for (int l = 0; l < 4; l++){
        int p = tid + l * 64;
        int dl = p >> 5, bb = p & 31;
        float gi = gsm[dl][bb], gf = gsm[8 + dl][bb];
        float gg = gsm[16 + dl][bb], go = gsm[24 + dl][bb];
        int idx = bb * DDIM + d0 + dl;
        float cn = sigf(gf) * g_c0[idx] + sigf(gi) * tanhf(gg);
        sout[idx] = sigf(go) * tanhf(cn);
        g_c0[idx] = cn;
    }
}

// ------------- LSTM cell, layer 1 (x = new s0, state s1), K = 512+512 -------------
__global__ void k_cell1(int t, const float* __restrict__ Wih, const float* __restrict__ Whh,
                        const float* __restrict__ bih, const float* __restrict__ bhh){
    __shared__ __align__(16) float St[64][36];
    __shared__ __align__(16) float Wt[64][36];
    __shared__ float gsm[32][33];
    const int tid = threadIdx.x;                 // 64
    const int d0 = blockIdx.x * 8;
    const int ping = t & 1;
    const float* Sx = g_s0[ping ^ 1];
    const float* Sh = g_s1[ping];
    const int rg = tid >> 3, bg = tid & 7;
    const int lr0 = rg * 4, b0 = bg * 4;
    float acc[4][4] = {};
    for (int c = 0; c < 16; c++){
        const float* S = (c < 8) ? Sx : Sh;
        const float* W = (c < 8) ? Wih : Whh;
        int kof = (c & 7) * 64;
        #pragma unroll 4
        for (int l = 0; l < 32; l++){
            St[tid][l] = S[l * DDIM + kof + tid];
            int r = (l >> 3) * DDIM + d0 + (l & 7);
            Wt[tid][l] = W[r * DDIM + kof + tid];
        }
        __syncthreads();
        #pragma unroll 8
        for (int k = 0; k < 64; k++){
            float rw[4], rs[4];
            #pragma unroll
            for (int i = 0; i < 4; i++) rw[i] = Wt[k][lr0 + i];
            #pragma unroll
            for (int j = 0; j < 4; j++) rs[j] = St[k][b0 + j];
            #pragma unroll
            for (int i = 0; i < 4; i++)
                #pragma unroll
                for (int j = 0; j < 4; j++) acc[i][j] += rw[i] * rs[j];
        }
        __syncthreads();
    }
    #pragma unroll
    for (int i = 0; i < 4; i++){
        int lr = lr0 + i;
        int r  = (lr >> 3) * DDIM + d0 + (lr & 7);
        float bsum = bih[r] + bhh[r];
        #pragma unroll
        for (int j = 0; j < 4; j++){
            int bb = b0 + j;
            gsm[lr][bb] = acc[i][j] + bsum;
        }
    }
    __syncthreads();
    float* sout = g_s1[ping ^ 1];
    #pragma unroll
    for (int l = 0; l < 4; l++){
        int p = tid + l * 64;
        int dl = p >> 5, bb = p & 31;
        float gi = gsm[dl][bb], gf = gsm[8 + dl][bb];
        float gg = gsm[16 + dl][bb], go = gsm[24 + dl][bb];
        int d = d0 + dl;
        int idx = bb * DDIM + d;
        float cn = sigf(gf) * g_c1[idx] + sigf(gi) * tanhf(gg);
        float sn = sigf(go) * tanhf(cn);
        sout[idx] = sn;
        g_c1[idx] = cn;
        g_A[((size_t)bb * TDIM + t) * (2 * DDIM) + d] = sn;   // first half of A row
    }
}

// ------------- attention: scores, softmax, context; writes z into A[.., 512:1024] -------------
__global__ void k_attn(int t, const float* __restrict__ h){
    __shared__ float s1s[512];
    __shared__ float sc[128];
    __shared__ float red[4];
    const int b = blockIdx.x;
    const int tid = threadIdx.x;              // 128
    const int w = tid >> 5, lane = tid & 31;
    const float* s1n = g_s1[(t & 1) ^ 1] + b * DDIM;
    for (int i = tid; i < DDIM; i += 128) s1s[i] = s1n[i];
    __syncthreads();
    const float* hb = h + (size_t)b * SDIM * DDIM;
    for (int so = 0; so < 32; so++){
        int s = w * 32 + so;
        const float* hr = hb + (size_t)s * DDIM;
        float p = 0.0f;
        #pragma unroll
        for (int j = 0; j < 16; j++) p += hr[lane + 32 * j] * s1s[lane + 32 * j];
        #pragma unroll
        for (int off = 16; off; off >>= 1) p += __shfl_xor_sync(0xffffffffu, p, off);
        if (lane == 0) sc[s] = p;
    }
    __syncthreads();
    float v = sc[tid];
    float mx = v;
    #pragma unroll
    for (int off = 16; off; off >>= 1) mx = fmaxf(mx, __shfl_xor_sync(0xffffffffu, mx, off));
    if (lane == 0) red[w] = mx;
    __syncthreads();
    mx = fmaxf(fmaxf(red[0], red[1]), fmaxf(red[2], red[3]));
    float e = expf(v - mx);
    float sm = e;
    #pragma unroll
    for (int off = 16; off; off >>= 1) sm += __shfl_xor_sync(0xffffffffu, sm, off);
    __syncthreads();
    if (lane == 0) red[w] = sm;
    __syncthreads();
    sm = red[0] + red[1] + red[2] + red[3];
    sc[tid] = e / sm;
    __syncthreads();
    float4 acc = make_float4(0.f, 0.f, 0.f, 0.f);
    for (int s = 0; s < SDIM; s++){
        float a = sc[s];
        float4 hv = *(const float4*)(hb + (size_t)s * DDIM + tid * 4);
        acc.x += a * hv.x; acc.y += a * hv.y; acc.z += a * hv.z; acc.w += a * hv.w;
    }
    float* Az = g_A + ((size_t)b * TDIM + t) * (2 * DDIM) + DDIM;
    *(float4*)(Az + tid * 4) = acc;
}

// ------------- output GEMM: Out = A @ Wout^T + bout -------------
// M=4096 (row = b*T+t), N=32000, K=1024. 128x128 tile, 256 thr, 8x8/thread, f32x2.
__global__ void __launch_bounds__(256) k_out(float* __restrict__ out,
                                             const float* __restrict__ Wout,
                                             const float* __restrict__ bout){
    __shared__ __align__(16) float As[8][132];
    __shared__ __align__(16) float Bs[8][132];
    const int tid = threadIdx.x;
    const int m0 = blockIdx.x * 128, n0 = blockIdx.y * 128;
    const int ty = tid >> 4, tx = tid & 15;
    const int ml0 = ty * 8, nl0 = tx * 8;
    const int lr = tid >> 1, lq = (tid & 1) * 4;
    unsigned long long acc[4][8];
    #pragma unroll
    for (int i = 0; i < 4; i++)
        #pragma unroll
        for (int j = 0; j < 8; j++) acc[i][j] = 0ull;

    for (int kc = 0; kc < 1024; kc += 8){
        float4 av = *(const float4*)(g_A  + (size_t)(m0 + lr) * 1024 + kc + lq);
        float4 bv = *(const float4*)(Wout + (size_t)(n0 + lr) * 1024 + kc + lq);
        As[lq + 0][lr] = av.x; As[lq + 1][lr] = av.y; As[lq + 2][lr] = av.z; As[lq + 3][lr] = av.w;
        Bs[lq + 0][lr] = bv.x; Bs[lq + 1][lr] = bv.y; Bs[lq + 2][lr] = bv.z; Bs[lq + 3][lr] = bv.w;
        __syncthreads();
        #pragma unroll
        for (int k = 0; k < 8; k++){
            ulonglong2 a01 = *(const ulonglong2*)&As[k][ml0];
            ulonglong2 a23 = *(const ulonglong2*)&As[k][ml0 + 4];
            unsigned long long a2[4] = { a01.x, a01.y, a23.x, a23.y };
            float4 bA = *(const float4*)&Bs[k][nl0];
            float4 bB = *(const float4*)&Bs[k][nl0 + 4];
            float rb[8] = { bA.x, bA.y, bA.z, bA.w, bB.x, bB.y, bB.z, bB.w };
            #pragma unroll
            for (int j = 0; j < 8; j++){
                unsigned long long bs = splat2(rb[j]);
                #pragma unroll
                for (int i = 0; i < 4; i++) ffma2(acc[i][j], a2[i], bs);
            }
        }
        __syncthreads();
    }
    const int bb = blockIdx.x;   // one m-tile == one batch (rows b*128 + t)
    #pragma unroll
    for (int j = 0; j < 8; j++){
        int v = n0 + nl0 + j;
        unsigned long long bj = splat2(bout[v]);
        ulonglong2 s0v, s1v;
        s0v.x = add2(acc[0][j], bj); s0v.y = add2(acc[1][j], bj);
        s1v.x = add2(acc[2][j], bj); s1v.y = add2(acc[3][j], bj);
        ulonglong2* po = (ulonglong2*)(out + ((size_t)bb * VSZ + v) * TDIM + ml0);
        po[0] = s0v;
        po[1] = s1v;
    }
}

// ------------- launcher -------------
extern "C" void kernel_launch(void* const* d_in, const int* in_sizes, int n_in,
                              void* d_out, int out_size){
    const int*   tar  = (const int*)  d_in[0];
    const float* h    = (const float*)d_in[1];
    const float* s0   = (const float*)d_in[2];
    const float* c0   = (const float*)d_in[3];
    const float* emb  = (const float*)d_in[4];
    const float* Wih0 = (const float*)d_in[5];
    const float* Whh0 = (const float*)d_in[6];
    const float* bih0 = (const float*)d_in[7];
    const float* bhh0 = (const float*)d_in[8];
    const float* Wih1 = (const float*)d_in[9];
    const float* Whh1 = (const float*)d_in[10];
    const float* bih1 = (const float*)d_in[11];
    const float* bhh1 = (const float*)d_in[12];
    const float* Wout = (const float*)d_in[13];
    const float* bout = (const float*)d_in[14];
    float* out = (float*)d_out;

    k_init<<<64, 256>>>(s0, c0);
    k_x0<<<dim3(32, 64), 256>>>(tar, emb, Wih0, bih0, bhh0);
    for (int t = 0; t < TDIM; t++){
        k_cell0<<<64, 64>>>(t, Whh0);
        k_cell1<<<64, 64>>>(t, Wih1, Whh1, bih1, bhh1);
        k_attn<<<32, 128>>>(t, h);
    }
    k_out<<<dim3(32, 250), 256>>>(out, Wout, bout);
}

// round 4
// speedup vs baseline: 2.6785x; 2.6785x over previous
#include <cuda_runtime.h>
#include <math.h>

#define VSZ  32000
#define EDIM 256
#define DDIM 512
#define BDIM 32
#define TDIM 128
#define SDIM 128
#define PADI 3
#define G4D  2048
#define NCTA 128
#define NTHR 256

// ------------- static device scratch -------------
__device__ float g_X0[(size_t)TDIM * BDIM * G4D];          // 33.5 MB
__device__ float g_A [(size_t)BDIM * TDIM * 2 * DDIM];     // 16.8 MB, row = b*T+t
__device__ float g_s0[2][BDIM * DDIM];
__device__ float g_s1[2][BDIM * DDIM];
__device__ unsigned g_bar_cnt = 0;
__device__ unsigned g_bar_gen = 0;

__device__ __forceinline__ float sigf(float x){ return 1.0f / (1.0f + expf(-x)); }

// ------------- packed f32x2 helpers (k_out) -------------
__device__ __forceinline__ unsigned long long splat2(float x){
    unsigned long long u; unsigned r = __float_as_uint(x);
    asm("mov.b64 %0, {%1, %1};" : "=l"(u) : "r"(r));
    return u;
}
__device__ __forceinline__ void ffma2(unsigned long long& d, unsigned long long a, unsigned long long b){
    asm("fma.rn.f32x2 %0, %1, %2, %3;" : "=l"(d) : "l"(a), "l"(b), "l"(d));
}
__device__ __forceinline__ unsigned long long add2(unsigned long long a, unsigned long long b){
    unsigned long long d;
    asm("add.rn.f32x2 %0, %1, %2;" : "=l"(d) : "l"(a), "l"(b));
    return d;
}

// ------------- init recurrent state -------------
__global__ void k_init(const float* __restrict__ s0, const float* __restrict__ c0){
    int i = blockIdx.x * 256 + threadIdx.x;
    if (i < BDIM * DDIM){
        g_s0[0][i] = s0[i];
        g_s1[0][i] = s0[BDIM * DDIM + i];
    }
}

// ------------- X0 = emb_eff[tok] @ Wih0^T + bih0 + bhh0 -------------
__global__ void k_x0(const int* __restrict__ tar, const float* __restrict__ emb,
                     const float* __restrict__ W, const float* __restrict__ b1,
                     const float* __restrict__ b2){
    __shared__ __align__(16) float Ast[32][68];
    __shared__ __align__(16) float Bst[32][68];
    const int tid = threadIdx.x;
    const int n0 = blockIdx.x * 64, m0 = blockIdx.y * 64;
    const int mg = tid >> 4, ng = tid & 15;
    const int ml0 = mg * 4, nl0 = ng * 4;
    const int kl = tid & 31, rl = tid >> 5;
    float acc[4][4] = {};
    for (int kc = 0; kc < EDIM; kc += 32){
        #pragma unroll
        for (int l = 0; l < 8; l++){
            int ml = rl + l * 8;
            int m  = m0 + ml;
            int tt = m >> 5, bb = m & 31;
            int tok = tar[bb * TDIM + tt];
            Ast[kl][ml] = (tok == PADI) ? 0.0f : emb[tok * EDIM + kc + kl];
            int nl = rl + l * 8;
            Bst[kl][nl] = W[(n0 + nl) * EDIM + kc + kl];
        }
        __syncthreads();
        #pragma unroll 8
        for (int k = 0; k < 32; k++){
            float ra[4], rb[4];
            #pragma unroll
            for (int i = 0; i < 4; i++) ra[i] = Ast[k][ml0 + i];
            #pragma unroll
            for (int j = 0; j < 4; j++) rb[j] = Bst[k][nl0 + j];
            #pragma unroll
            for (int i = 0; i < 4; i++)
                #pragma unroll
                for (int j = 0; j < 4; j++) acc[i][j] += ra[i] * rb[j];
        }
        __syncthreads();
    }
    #pragma unroll
    for (int i = 0; i < 4; i++){
        int m = m0 + ml0 + i;
        #pragma unroll
        for (int j = 0; j < 4; j++){
            int n = n0 + nl0 + j;
            g_X0[(size_t)m * G4D + n] = acc[i][j] + b1[n] + b2[n];
        }
    }
}

// ------------- persistent recurrence kernel -------------
// 128 CTAs x 256 thr, 1 CTA/SM (smem-bound) => co-resident; software grid barrier.
// CTA c owns d-slice [4c, 4c+4) for both layers: 16 gate rows each, weights in SMEM.
#define W0STR 129   // float4 row stride (128 + 1 pad)
#define W1STR 257   // float4 row stride (256 + 1 pad)
#define SSTR  37    // float4 stride between k-groups in S4

struct RecSmem {
    float4 W0[16 * W0STR];
    float4 W1[16 * W1STR];
    float4 S4[64 * SSTR];      // staged input chunk: [kq][b] (f4 over 4 k)
    float  gpart[4 * 16 * 32]; // [kgroup][row][batch]
    float  csm0[128];
    float  csm1[128];
    float  bsum[16];
    float  s1s[512];
    float  sc[128];
    float  red[4];
    unsigned gen0;
};

__device__ __forceinline__ void gridbar(unsigned target){
    __syncthreads();
    if (threadIdx.x == 0){
        __threadfence();
        unsigned a = atomicAdd(&g_bar_cnt, 1u);
        if (a == NCTA - 1u){
            g_bar_cnt = 0u;
            __threadfence();
            atomicAdd(&g_bar_gen, 1u);
        } else {
            volatile unsigned* p = &g_bar_gen;
            while ((int)(*p - target) < 0) __nanosleep(64);
        }
        __threadfence();
    }
    __syncthreads();
}

__global__ void __launch_bounds__(NTHR, 1) k_rec(
    const float* __restrict__ h,   const float* __restrict__ c0in,
    const float* __restrict__ Whh0,
    const float* __restrict__ Wih1, const float* __restrict__ Whh1,
    const float* __restrict__ bih1, const float* __restrict__ bhh1)
{
    extern __shared__ RecSmem sm[];
    const int tid = threadIdx.x;
    const int d0  = blockIdx.x * 4;

    // ---- prologue: weights + biases + c-state into SMEM, capture barrier gen ----
    if (tid == 0) sm->gen0 = *(volatile unsigned*)&g_bar_gen;
    for (int i = tid; i < 16 * 128; i += NTHR){
        int r_l = i >> 7, kq = i & 127;
        int gr  = (r_l >> 2) * DDIM + d0 + (r_l & 3);
        sm->W0[r_l * W0STR + kq] = *(const float4*)(Whh0 + (size_t)gr * DDIM + kq * 4);
    }
    for (int i = tid; i < 16 * 256; i += NTHR){
        int r_l = i >> 8, kq = i & 255;
        int gr  = (r_l >> 2) * DDIM + d0 + (r_l & 3);
        float4 v;
        if (kq < 128) v = *(const float4*)(Wih1 + (size_t)gr * DDIM + kq * 4);
        else          v = *(const float4*)(Whh1 + (size_t)gr * DDIM + (kq - 128) * 4);
        sm->W1[r_l * W1STR + kq] = v;
    }
    if (tid < 16){
        int gr = (tid >> 2) * DDIM + d0 + (tid & 3);
        sm->bsum[tid] = bih1[gr] + bhh1[gr];
    }
    if (tid < 128){
        int dl = tid >> 5, b = tid & 31;
        sm->csm0[tid] = c0in[b * DDIM + d0 + dl];
        sm->csm1[tid] = c0in[BDIM * DDIM + b * DDIM + d0 + dl];
    }
    __syncthreads();
    const unsigned gen0 = sm->gen0;

    const int g3 = tid >> 6;        // k-split group 0..3
    const int l  = tid & 63;
    const int rq = l >> 3;          // 0..7 -> rows 2rq, 2rq+1
    const int bq = l & 7;           // batches bq, bq+8, bq+16, bq+24

    for (int t = 0; t < TDIM; t++){
        const int ping = t & 1;

        // ================= cell0: gates0 = X0[t] + s0 @ Whh0^T =================
        float acc[2][4] = {};
        const float* Sg = g_s0[ping];
        #pragma unroll 1
        for (int c = 0; c < 2; c++){
            int kc4 = c * 64;
            for (int i = tid; i < 2048; i += NTHR){
                int kq = i & 63, b = i >> 6;
                sm->S4[kq * SSTR + (b >> 3) * 8 + (b & 7)] =
                    *(const float4*)(Sg + b * DDIM + (kc4 + kq) * 4);
            }
            __syncthreads();
            const float4* w0p = sm->W0 + (2 * rq)     * W0STR + kc4 + g3 * 16;
            const float4* w1p = sm->W0 + (2 * rq + 1) * W0STR + kc4 + g3 * 16;
            const float4* sp  = sm->S4 + (g3 * 16) * SSTR + bq;
            #pragma unroll 8
            for (int kk = 0; kk < 16; kk++){
                float4 w0 = w0p[kk], w1 = w1p[kk];
                float4 sv[4];
                sv[0] = sp[kk * SSTR + 0];  sv[1] = sp[kk * SSTR + 8];
                sv[2] = sp[kk * SSTR + 16]; sv[3] = sp[kk * SSTR + 24];
                #pragma unroll
                for (int j = 0; j < 4; j++){
                    acc[0][j] += w0.x * sv[j].x + w0.y * sv[j].y + w0.z * sv[j].z + w0.w * sv[j].w;
                    acc[1][j] += w1.x * sv[j].x + w1.y * sv[j].y + w1.z * sv[j].z + w1.w * sv[j].w;
                }
            }
            __syncthreads();
        }
        #pragma unroll
        for (int i = 0; i < 2; i++)
            #pragma unroll
            for (int j = 0; j < 4; j++)
                sm->gpart[(g3 * 16 + 2 * rq + i) * 32 + (bq + 8 * j)] = acc[i][j];
        __syncthreads();
        if (tid < 128){
            int dl = tid >> 5, b = tid & 31;
            float gv[4];
            #pragma unroll
            for (int q = 0; q < 4; q++){
                int r_l = q * 4 + dl;
                gv[q] = sm->gpart[(0 * 16 + r_l) * 32 + b] + sm->gpart[(1 * 16 + r_l) * 32 + b]
                      + sm->gpart[(2 * 16 + r_l) * 32 + b] + sm->gpart[(3 * 16 + r_l) * 32 + b]
                      + g_X0[((size_t)t * BDIM + b) * G4D + q * DDIM + d0 + dl];
            }
            float cn = sigf(gv[1]) * sm->csm0[tid] + sigf(gv[0]) * tanhf(gv[2]);
            sm->csm0[tid] = cn;
            g_s0[ping ^ 1][b * DDIM + d0 + dl] = sigf(gv[3]) * tanhf(cn);
        }
        gridbar(gen0 + 2 * t + 1);

        // ================= cell1: gates1 = [s0new ; s1] @ [Wih1 ; Whh1]^T + b =================
        float acc1[2][4] = {};
        #pragma unroll 1
        for (int c = 0; c < 4; c++){
            const float* Ss = (c < 2) ? g_s0[ping ^ 1] : g_s1[ping];
            int koff = (c & 1) * 64;
            for (int i = tid; i < 2048; i += NTHR){
                int kq = i & 63, b = i >> 6;
                sm->S4[kq * SSTR + b] = *(const float4*)(Ss + b * DDIM + (koff + kq) * 4);
            }
            __syncthreads();
            const float4* w0p = sm->W1 + (2 * rq)     * W1STR + c * 64 + g3 * 16;
            const float4* w1p = sm->W1 + (2 * rq + 1) * W1STR + c * 64 + g3 * 16;
            const float4* sp  = sm->S4 + (g3 * 16) * SSTR + bq;
            #pragma unroll 8
            for (int kk = 0; kk < 16; kk++){
                float4 w0 = w0p[kk], w1 = w1p[kk];
                float4 sv[4];
                sv[0] = sp[kk * SSTR + 0];  sv[1] = sp[kk * SSTR + 8];
                sv[2] = sp[kk * SSTR + 16]; sv[3] = sp[kk * SSTR + 24];
                #pragma unroll
                for (int j = 0; j < 4; j++){
                    acc1[0][j] += w0.x * sv[j].x + w0.y * sv[j].y + w0.z * sv[j].z + w0.w * sv[j].w;
                    acc1[1][j] += w1.x * sv[j].x + w1.y * sv[j].y + w1.z * sv[j].z + w1.w * sv[j].w;
                }
            }
            __syncthreads();
        }
        #pragma unroll
        for (int i = 0; i < 2; i++)
            #pragma unroll
            for (int j = 0; j < 4; j++)
                sm->gpart[(g3 * 16 + 2 * rq + i) * 32 + (bq + 8 * j)] = acc1[i][j];
        __syncthreads();
        if (tid < 128){
            int dl = tid >> 5, b = tid & 31;
            float gv[4];
            #pragma unroll
            for (int q = 0; q < 4; q++){
                int r_l = q * 4 + dl;
                gv[q] = sm->gpart[(0 * 16 + r_l) * 32 + b] + sm->gpart[(1 * 16 + r_l) * 32 + b]
                      + sm->gpart[(2 * 16 + r_l) * 32 + b] + sm->gpart[(3 * 16 + r_l) * 32 + b]
                      + sm->bsum[r_l];
            }
            float cn = sigf(gv[1]) * sm->csm1[tid] + sigf(gv[0]) * tanhf(gv[2]);
            sm->csm1[tid] = cn;
            float sn = sigf(gv[3]) * tanhf(cn);
            g_s1[ping ^ 1][b * DDIM + d0 + dl] = sn;
            g_A[((size_t)b * TDIM + t) * (2 * DDIM) + d0 + dl] = sn;
        }
        gridbar(gen0 + 2 * t + 2);

        // ================= attention (CTAs 0..31, runs inside next cell0 phase) =================
        if (blockIdx.x < BDIM){
            const int b = blockIdx.x;
            const float* s1n = g_s1[ping ^ 1] + b * DDIM;
            for (int i = tid; i < DDIM; i += NTHR) sm->s1s[i] = s1n[i];
            __syncthreads();
            const float* hb = h + (size_t)b * SDIM * DDIM;
            int w = tid >> 5, lane = tid & 31;
            for (int so = 0; so < 16; so++){
                int s = w * 16 + so;
                const float* hr = hb + (size_t)s * DDIM;
                float p = 0.0f;
                #pragma unroll
                for (int j2 = 0; j2 < 16; j2++) p += hr[lane + 32 * j2] * sm->s1s[lane + 32 * j2];
                #pragma unroll
                for (int off = 16; off; off >>= 1) p += __shfl_xor_sync(0xffffffffu, p, off);
                if (lane == 0) sm->sc[s] = p;
            }
            __syncthreads();
            if (tid < 128){
                float v = sm->sc[tid];
                float mx = v;
                #pragma unroll
                for (int off = 16; off; off >>= 1) mx = fmaxf(mx, __shfl_xor_sync(0xffffffffu, mx, off));
                if (lane == 0) sm->red[w] = mx;
            }
            __syncthreads();
            if (tid < 128){
                float mx = fmaxf(fmaxf(sm->red[0], sm->red[1]), fmaxf(sm->red[2], sm->red[3]));
                float e = expf(sm->sc[tid] - mx);
                float smv = e;
                #pragma unroll
                for (int off = 16; off; off >>= 1) smv += __shfl_xor_sync(0xffffffffu, smv, off);
                __syncwarp();
                if (lane == 0) sm->red[w] = smv;
                sm->s1s[tid] = e;   // stash numerator
            }
            __syncthreads();
            if (tid < 128){
                float smv = sm->red[0] + sm->red[1] + sm->red[2] + sm->red[3];
                sm->sc[tid] = sm->s1s[tid] / smv;
            }
            __syncthreads();
            float2 accz = make_float2(0.f, 0.f);
            int d2 = tid * 2;
            #pragma unroll 4
            for (int s = 0; s < SDIM; s++){
                float a = sm->sc[s];
                float2 hv = *(const float2*)(hb + (size_t)s * DDIM + d2);
                accz.x += a * hv.x; accz.y += a * hv.y;
            }
            *(float2*)(g_A + ((size_t)b * TDIM + t) * (2 * DDIM) + DDIM + d2) = accz;
            __syncthreads();
        }
    }
}

// ------------- output GEMM: Out = A @ Wout^T + bout -------------
__global__ void __launch_bounds__(256) k_out(float* __restrict__ out,
                                             const float* __restrict__ Wout,
                                             const float* __restrict__ bout){
    __shared__ __align__(16) float As[8][132];
    __shared__ __align__(16) float Bs[8][132];
    const int tid = threadIdx.x;
    const int m0 = blockIdx.x * 128, n0 = blockIdx.y * 128;
    const int ty = tid >> 4, tx = tid & 15;
    const int ml0 = ty * 8, nl0 = tx * 8;
    const int lr = tid >> 1, lq = (tid & 1) * 4;
    unsigned long long acc[4][8];
    #pragma unroll
    for (int i = 0; i < 4; i++)
        #pragma unroll
        for (int j = 0; j < 8; j++) acc[i][j] = 0ull;

    for (int kc = 0; kc < 1024; kc += 8){
        float4 av = *(const float4*)(g_A  + (size_t)(m0 + lr) * 1024 + kc + lq);
        float4 bv = *(const float4*)(Wout + (size_t)(n0 + lr) * 1024 + kc + lq);
        As[lq + 0][lr] = av.x; As[lq + 1][lr] = av.y; As[lq + 2][lr] = av.z; As[lq + 3][lr] = av.w;
        Bs[lq + 0][lr] = bv.x; Bs[lq + 1][lr] = bv.y; Bs[lq + 2][lr] = bv.z; Bs[lq + 3][lr] = bv.w;
        __syncthreads();
        #pragma unroll
        for (int k = 0; k < 8; k++){
            ulonglong2 a01 = *(const ulonglong2*)&As[k][ml0];
            ulonglong2 a23 = *(const ulonglong2*)&As[k][ml0 + 4];
            unsigned long long a2[4] = { a01.x, a01.y, a23.x, a23.y };
            float4 bA = *(const float4*)&Bs[k][nl0];
            float4 bB = *(const float4*)&Bs[k][nl0 + 4];
            float rb[8] = { bA.x, bA.y, bA.z, bA.w, bB.x, bB.y, bB.z, bB.w };
            #pragma unroll
            for (int j = 0; j < 8; j++){
                unsigned long long bs = splat2(rb[j]);
                #pragma unroll
                for (int i = 0; i < 4; i++) ffma2(acc[i][j], a2[i], bs);
            }
        }
        __syncthreads();
    }
    const int bb = blockIdx.x;
    #pragma unroll
    for (int j = 0; j < 8; j++){
        int v = n0 + nl0 + j;
        unsigned long long bj = splat2(bout[v]);
        ulonglong2 s0v, s1v;
        s0v.x = add2(acc[0][j], bj); s0v.y = add2(acc[1][j], bj);
        s1v.x = add2(acc[2][j], bj); s1v.y = add2(acc[3][j], bj);
        ulonglong2* po = (ulonglong2*)(out + ((size_t)bb * VSZ + v) * TDIM + ml0);
        po[0] = s0v;
        po[1] = s1v;
    }
}

// ------------- launcher -------------
extern "C" void kernel_launch(void* const* d_in, const int* in_sizes, int n_in,
                              void* d_out, int out_size){
    const int*   tar  = (const int*)  d_in[0];
    const float* h    = (const float*)d_in[1];
    const float* s0   = (const float*)d_in[2];
    const float* c0   = (const float*)d_in[3];
    const float* emb  = (const float*)d_in[4];
    const float* Wih0 = (const float*)d_in[5];
    const float* bih0 = (const float*)d_in[7];
    const float* bhh0 = (const float*)d_in[8];
    const float* Whh0 = (const float*)d_in[6];
    const float* Wih1 = (const float*)d_in[9];
    const float* Whh1 = (const float*)d_in[10];
    const float* bih1 = (const float*)d_in[11];
    const float* bhh1 = (const float*)d_in[12];
    const float* Wout = (const float*)d_in[13];
    const float* bout = (const float*)d_in[14];
    float* out = (float*)d_out;

    static int smem_set = 0;
    if (!smem_set){
        cudaFuncSetAttribute(k_rec, cudaFuncAttributeMaxDynamicSharedMemorySize,
                             (int)sizeof(RecSmem));
        smem_set = 1;
    }

    k_init<<<64, 256>>>(s0, c0);
    k_x0<<<dim3(32, 64), 256>>>(tar, emb, Wih0, bih0, bhh0);
    k_rec<<<NCTA, NTHR, sizeof(RecSmem)>>>(h, c0, Whh0, Wih1, Whh1, bih1, bhh1);
    k_out<<<dim3(32, 250), 256>>>(out, Wout, bout);
}

// round 7
// speedup vs baseline: 4.5450x; 1.6969x over previous
#include <cuda_runtime.h>
#include <cuda_bf16.h>
#include <math.h>
#include <stdint.h>

#define VSZ  32000
#define EDIM 256
#define DDIM 512
#define BDIM 32
#define TDIM 128
#define SDIM 128
#define PADI 3
#define G4D  2048
#define NCTA 128
#define NTHR 256

// ------------- static device scratch -------------
__device__ float g_X0[(size_t)TDIM * BDIM * G4D];          // 33.5 MB
__device__ float g_A [(size_t)BDIM * TDIM * 2 * DDIM];     // 16.8 MB, row = b*T+t
__device__ float g_s0[2][BDIM * DDIM];
__device__ float g_s1[2][BDIM * DDIM];
__device__ unsigned g_bar_cnt = 0;
__device__ unsigned g_bar_gen = 0;

// bf16 split operands for the big GEMM
__device__ __nv_bfloat16 g_Ah[(size_t)4096 * 1024];
__device__ __nv_bfloat16 g_Al[(size_t)4096 * 1024];
__device__ __nv_bfloat16 g_Bh[(size_t)VSZ * 1024];
__device__ __nv_bfloat16 g_Bl[(size_t)VSZ * 1024];

__device__ __forceinline__ float sigf(float x){ return 1.0f / (1.0f + expf(-x)); }

__device__ __forceinline__ uint32_t smem_u32(const void* p){
    uint32_t a;
    asm("{ .reg .u64 t; cvta.to.shared.u64 t, %1; cvt.u32.u64 %0, t; }" : "=r"(a) : "l"(p));
    return a;
}

#define CP_ASYNC16(dst, src) \
    asm volatile("cp.async.cg.shared.global [%0], [%1], 16;" :: "r"(dst), "l"(src))
#define CP_COMMIT() asm volatile("cp.async.commit_group;" ::: "memory")
#define CP_WAIT(n)  asm volatile("cp.async.wait_group %0;" :: "n"(n) : "memory")

#define LDSM4(r, a) \
    asm volatile("ldmatrix.sync.aligned.m8n8.x4.shared.b16 {%0,%1,%2,%3}, [%4];" \
        : "=r"((r)[0]), "=r"((r)[1]), "=r"((r)[2]), "=r"((r)[3]) : "r"(a))
#define LDSM2(r, a) \
    asm volatile("ldmatrix.sync.aligned.m8n8.x2.shared.b16 {%0,%1}, [%2];" \
        : "=r"((r)[0]), "=r"((r)[1]) : "r"(a))
#define MMA_BF16(d, a, b) \
    asm volatile("mma.sync.aligned.m16n8k16.row.col.f32.bf16.bf16.f32 " \
        "{%0,%1,%2,%3}, {%4,%5,%6,%7}, {%8,%9}, {%0,%1,%2,%3};" \
        : "+f"((d)[0]), "+f"((d)[1]), "+f"((d)[2]), "+f"((d)[3]) \
        : "r"((a)[0]), "r"((a)[1]), "r"((a)[2]), "r"((a)[3]), "r"((b)[0]), "r"((b)[1]))

// ------------- init recurrent state -------------
__global__ void k_init(const float* __restrict__ s0, const float* __restrict__ c0){
    int i = blockIdx.x * 256 + threadIdx.x;
    if (i < BDIM * DDIM){
        g_s0[0][i] = s0[i];
        g_s1[0][i] = s0[BDIM * DDIM + i];
    }
}

// ------------- X0 = emb_eff[tok] @ Wih0^T + bih0 + bhh0 -------------
__global__ void k_x0(const int* __restrict__ tar, const float* __restrict__ emb,
                     const float* __restrict__ W, const float* __restrict__ b1,
                     const float* __restrict__ b2){
    __shared__ __align__(16) float Ast[32][68];
    __shared__ __align__(16) float Bst[32][68];
    const int tid = threadIdx.x;
    const int n0 = blockIdx.x * 64, m0 = blockIdx.y * 64;
    const int mg = tid >> 4, ng = tid & 15;
    const int ml0 = mg * 4, nl0 = ng * 4;
    const int kl = tid & 31, rl = tid >> 5;
    float acc[4][4] = {};
    for (int kc = 0; kc < EDIM; kc += 32){
        #pragma unroll
        for (int l = 0; l < 8; l++){
            int ml = rl + l * 8;
            int m  = m0 + ml;
            int tt = m >> 5, bb = m & 31;
            int tok = tar[bb * TDIM + tt];
            Ast[kl][ml] = (tok == PADI) ? 0.0f : emb[tok * EDIM + kc + kl];
            int nl = rl + l * 8;
            Bst[kl][nl] = W[(n0 + nl) * EDIM + kc + kl];
        }
        __syncthreads();
        #pragma unroll 8
        for (int k = 0; k < 32; k++){
            float ra[4], rb[4];
            #pragma unroll
            for (int i = 0; i < 4; i++) ra[i] = Ast[k][ml0 + i];
            #pragma unroll
            for (int j = 0; j < 4; j++) rb[j] = Bst[k][nl0 + j];
            #pragma unroll
            for (int i = 0; i < 4; i++)
                #pragma unroll
                for (int j = 0; j < 4; j++) acc[i][j] += ra[i] * rb[j];
        }
        __syncthreads();
    }
    #pragma unroll
    for (int i = 0; i < 4; i++){
        int m = m0 + ml0 + i;
        #pragma unroll
        for (int j = 0; j < 4; j++){
            int n = n0 + nl0 + j;
            g_X0[(size_t)m * G4D + n] = acc[i][j] + b1[n] + b2[n];
        }
    }
}

// ------------- persistent recurrence kernel (unchanged) -------------
#define W0STR 129
#define W1STR 257
#define SSTR  37

struct RecSmem {
    float4 W0[16 * W0STR];
    float4 W1[16 * W1STR];
    float4 S4[64 * SSTR];
    float  gpart[4 * 16 * 32];
    float  csm0[128];
    float  csm1[128];
    float  bsum[16];
    float  s1s[512];
    float  sc[128];
    float  red[4];
    unsigned gen0;
};

__device__ __forceinline__ void gridbar(unsigned target){
    __syncthreads();
    if (threadIdx.x == 0){
        __threadfence();
        unsigned a = atomicAdd(&g_bar_cnt, 1u);
        if (a == NCTA - 1u){
            g_bar_cnt = 0u;
            __threadfence();
            atomicAdd(&g_bar_gen, 1u);
        } else {
            volatile unsigned* p = &g_bar_gen;
            while ((int)(*p - target) < 0) __nanosleep(64);
        }
        __threadfence();
    }
    __syncthreads();
}

__global__ void __launch_bounds__(NTHR, 1) k_rec(
    const float* __restrict__ h,   const float* __restrict__ c0in,
    const float* __restrict__ Whh0,
    const float* __restrict__ Wih1, const float* __restrict__ Whh1,
    const float* __restrict__ bih1, const float* __restrict__ bhh1)
{
    extern __shared__ RecSmem sm[];
    const int tid = threadIdx.x;
    const int d0  = blockIdx.x * 4;

    if (tid == 0) sm->gen0 = *(volatile unsigned*)&g_bar_gen;
    for (int i = tid; i < 16 * 128; i += NTHR){
        int r_l = i >> 7, kq = i & 127;
        int gr  = (r_l >> 2) * DDIM + d0 + (r_l & 3);
        sm->W0[r_l * W0STR + kq] = *(const float4*)(Whh0 + (size_t)gr * DDIM + kq * 4);
    }
    for (int i = tid; i < 16 * 256; i += NTHR){
        int r_l = i >> 8, kq = i & 255;
        int gr  = (r_l >> 2) * DDIM + d0 + (r_l & 3);
        float4 v;
        if (kq < 128) v = *(const float4*)(Wih1 + (size_t)gr * DDIM + kq * 4);
        else          v = *(const float4*)(Whh1 + (size_t)gr * DDIM + (kq - 128) * 4);
        sm->W1[r_l * W1STR + kq] = v;
    }
    if (tid < 16){
        int gr = (tid >> 2) * DDIM + d0 + (tid & 3);
        sm->bsum[tid] = bih1[gr] + bhh1[gr];
    }
    if (tid < 128){
        int dl = tid >> 5, b = tid & 31;
        sm->csm0[tid] = c0in[b * DDIM + d0 + dl];
        sm->csm1[tid] = c0in[BDIM * DDIM + b * DDIM + d0 + dl];
    }
    __syncthreads();
    const unsigned gen0 = sm->gen0;

    const int g3 = tid >> 6;
    const int l  = tid & 63;
    const int rq = l >> 3;
    const int bq = l & 7;

    for (int t = 0; t < TDIM; t++){
        const int ping = t & 1;

        // cell0
        float acc[2][4] = {};
        const float* Sg = g_s0[ping];
        #pragma unroll 1
        for (int c = 0; c < 2; c++){
            int kc4 = c * 64;
            for (int i = tid; i < 2048; i += NTHR){
                int kq = i & 63, b = i >> 6;
                sm->S4[kq * SSTR + (b >> 3) * 8 + (b & 7)] =
                    *(const float4*)(Sg + b * DDIM + (kc4 + kq) * 4);
            }
            __syncthreads();
            const float4* w0p = sm->W0 + (2 * rq)     * W0STR + kc4 + g3 * 16;
            const float4* w1p = sm->W0 + (2 * rq + 1) * W0STR + kc4 + g3 * 16;
            const float4* sp  = sm->S4 + (g3 * 16) * SSTR + bq;
            #pragma unroll 8
            for (int kk = 0; kk < 16; kk++){
                float4 w0 = w0p[kk], w1 = w1p[kk];
                float4 sv[4];
                sv[0] = sp[kk * SSTR + 0];  sv[1] = sp[kk * SSTR + 8];
                sv[2] = sp[kk * SSTR + 16]; sv[3] = sp[kk * SSTR + 24];
                #pragma unroll
                for (int j = 0; j < 4; j++){
                    acc[0][j] += w0.x * sv[j].x + w0.y * sv[j].y + w0.z * sv[j].z + w0.w * sv[j].w;
                    acc[1][j] += w1.x * sv[j].x + w1.y * sv[j].y + w1.z * sv[j].z + w1.w * sv[j].w;
                }
            }
            __syncthreads();
        }
        #pragma unroll
        for (int i = 0; i < 2; i++)
            #pragma unroll
            for (int j = 0; j < 4; j++)
                sm->gpart[(g3 * 16 + 2 * rq + i) * 32 + (bq + 8 * j)] = acc[i][j];
        __syncthreads();
        if (tid < 128){
            int dl = tid >> 5, b = tid & 31;
            float gv[4];
            #pragma unroll
            for (int q = 0; q < 4; q++){
                int r_l = q * 4 + dl;
                gv[q] = sm->gpart[(0 * 16 + r_l) * 32 + b] + sm->gpart[(1 * 16 + r_l) * 32 + b]
                      + sm->gpart[(2 * 16 + r_l) * 32 + b] + sm->gpart[(3 * 16 + r_l) * 32 + b]
                      + g_X0[((size_t)t * BDIM + b) * G4D + q * DDIM + d0 + dl];
            }
            float cn = sigf(gv[1]) * sm->csm0[tid] + sigf(gv[0]) * tanhf(gv[2]);
            sm->csm0[tid] = cn;
            g_s0[ping ^ 1][b * DDIM + d0 + dl] = sigf(gv[3]) * tanhf(cn);
        }
        gridbar(gen0 + 2 * t + 1);

        // cell1
        float acc1[2][4] = {};
        #pragma unroll 1
        for (int c = 0; c < 4; c++){
            const float* Ss = (c < 2) ? g_s0[ping ^ 1] : g_s1[ping];
            int koff = (c & 1) * 64;
            for (int i = tid; i < 2048; i += NTHR){
                int kq = i & 63, b = i >> 6;
                sm->S4[kq * SSTR + b] = *(const float4*)(Ss + b * DDIM + (koff + kq) * 4);
            }
            __syncthreads();
            const float4* w0p = sm->W1 + (2 * rq)     * W1STR + c * 64 + g3 * 16;
            const float4* w1p = sm->W1 + (2 * rq + 1) * W1STR + c * 64 + g3 * 16;
            const float4* sp  = sm->S4 + (g3 * 16) * SSTR + bq;
            #pragma unroll 8
            for (int kk = 0; kk < 16; kk++){
                float4 w0 = w0p[kk], w1 = w1p[kk];
                float4 sv[4];
                sv[0] = sp[kk * SSTR + 0];  sv[1] = sp[kk * SSTR + 8];
                sv[2] = sp[kk * SSTR + 16]; sv[3] = sp[kk * SSTR + 24];
                #pragma unroll
                for (int j = 0; j < 4; j++){
                    acc1[0][j] += w0.x * sv[j].x + w0.y * sv[j].y + w0.z * sv[j].z + w0.w * sv[j].w;
                    acc1[1][j] += w1.x * sv[j].x + w1.y * sv[j].y + w1.z * sv[j].z + w1.w * sv[j].w;
                }
            }
            __syncthreads();
        }
        #pragma unroll
        for (int i = 0; i < 2; i++)
            #pragma unroll
            for (int j = 0; j < 4; j++)
                sm->gpart[(g3 * 16 + 2 * rq + i) * 32 + (bq + 8 * j)] = acc1[i][j];
        __syncthreads();
        if (tid < 128){
            int dl = tid >> 5, b = tid & 31;
            float gv[4];
            #pragma unroll
            for (int q = 0; q < 4; q++){
                int r_l = q * 4 + dl;
                gv[q] = sm->gpart[(0 * 16 + r_l) * 32 + b] + sm->gpart[(1 * 16 + r_l) * 32 + b]
                      + sm->gpart[(2 * 16 + r_l) * 32 + b] + sm->gpart[(3 * 16 + r_l) * 32 + b]
                      + sm->bsum[r_l];
            }
            float cn = sigf(gv[1]) * sm->csm1[tid] + sigf(gv[0]) * tanhf(gv[2]);
            sm->csm1[tid] = cn;
            float sn = sigf(gv[3]) * tanhf(cn);
            g_s1[ping ^ 1][b * DDIM + d0 + dl] = sn;
            g_A[((size_t)b * TDIM + t) * (2 * DDIM) + d0 + dl] = sn;
        }
        gridbar(gen0 + 2 * t + 2);

        // attention (CTAs 0..31)
        if (blockIdx.x < BDIM){
            const int b = blockIdx.x;
            const float* s1n = g_s1[ping ^ 1] + b * DDIM;
            for (int i = tid; i < DDIM; i += NTHR) sm->s1s[i] = s1n[i];
            __syncthreads();
            const float* hb = h + (size_t)b * SDIM * DDIM;
            int w = tid >> 5, lane = tid & 31;
            for (int so = 0; so < 16; so++){
                int s = w * 16 + so;
                const float* hr = hb + (size_t)s * DDIM;
                float p = 0.0f;
                #pragma unroll
                for (int j2 = 0; j2 < 16; j2++) p += hr[lane + 32 * j2] * sm->s1s[lane + 32 * j2];
                #pragma unroll
                for (int off = 16; off; off >>= 1) p += __shfl_xor_sync(0xffffffffu, p, off);
                if (lane == 0) sm->sc[s] = p;
            }
            __syncthreads();
            if (tid < 128){
                float v = sm->sc[tid];
                float mx = v;
                #pragma unroll
                for (int off = 16; off; off >>= 1) mx = fmaxf(mx, __shfl_xor_sync(0xffffffffu, mx, off));
                if (lane == 0) sm->red[w] = mx;
            }
            __syncthreads();
            if (tid < 128){
                float mx = fmaxf(fmaxf(sm->red[0], sm->red[1]), fmaxf(sm->red[2], sm->red[3]));
                float e = expf(sm->sc[tid] - mx);
                float smv = e;
                #pragma unroll
                for (int off = 16; off; off >>= 1) smv += __shfl_xor_sync(0xffffffffu, smv, off);
                __syncwarp();
                if (lane == 0) sm->red[w] = smv;
                sm->s1s[tid] = e;
            }
            __syncthreads();
            if (tid < 128){
                float smv = sm->red[0] + sm->red[1] + sm->red[2] + sm->red[3];
                sm->sc[tid] = sm->s1s[tid] / smv;
            }
            __syncthreads();
            float2 accz = make_float2(0.f, 0.f);
            int d2 = tid * 2;
            #pragma unroll 4
            for (int s = 0; s < SDIM; s++){
                float a = sm->sc[s];
                float2 hv = *(const float2*)(hb + (size_t)s * DDIM + d2);
                accz.x += a * hv.x; accz.y += a * hv.y;
            }
            *(float2*)(g_A + ((size_t)b * TDIM + t) * (2 * DDIM) + DDIM + d2) = accz;
            __syncthreads();
        }
    }
}

// ------------- bf16 hi/lo split conversions -------------
__global__ void k_cvtW(const float* __restrict__ W){
    const size_t total = (size_t)VSZ * 1024 / 4;
    for (size_t i = (size_t)blockIdx.x * blockDim.x + threadIdx.x; i < total;
         i += (size_t)gridDim.x * blockDim.x){
        float4 v = ((const float4*)W)[i];
        __nv_bfloat16 h0 = __float2bfloat16(v.x), h1 = __float2bfloat16(v.y);
        __nv_bfloat16 h2 = __float2bfloat16(v.z), h3 = __float2bfloat16(v.w);
        __nv_bfloat16 l0 = __float2bfloat16(v.x - __bfloat162float(h0));
        __nv_bfloat16 l1 = __float2bfloat16(v.y - __bfloat162float(h1));
        __nv_bfloat16 l2 = __float2bfloat16(v.z - __bfloat162float(h2));
        __nv_bfloat16 l3 = __float2bfloat16(v.w - __bfloat162float(h3));
        __nv_bfloat162 hp0 = __halves2bfloat162(h0, h1), hp1 = __halves2bfloat162(h2, h3);
        __nv_bfloat162 lp0 = __halves2bfloat162(l0, l1), lp1 = __halves2bfloat162(l2, l3);
        ((uint2*)g_Bh)[i] = make_uint2(*(unsigned*)&hp0, *(unsigned*)&hp1);
        ((uint2*)g_Bl)[i] = make_uint2(*(unsigned*)&lp0, *(unsigned*)&lp1);
    }
}
__global__ void k_cvtA(void){
    const size_t total = (size_t)4096 * 1024 / 4;
    for (size_t i = (size_t)blockIdx.x * blockDim.x + threadIdx.x; i < total;
         i += (size_t)gridDim.x * blockDim.x){
        float4 v = ((const float4*)g_A)[i];
        __nv_bfloat16 h0 = __float2bfloat16(v.x), h1 = __float2bfloat16(v.y);
        __nv_bfloat16 h2 = __float2bfloat16(v.z), h3 = __float2bfloat16(v.w);
        __nv_bfloat16 l0 = __float2bfloat16(v.x - __bfloat162float(h0));
        __nv_bfloat16 l1 = __float2bfloat16(v.y - __bfloat162float(h1));
        __nv_bfloat16 l2 = __float2bfloat16(v.z - __bfloat162float(h2));
        __nv_bfloat16 l3 = __float2bfloat16(v.w - __bfloat162float(h3));
        __nv_bfloat162 hp0 = __halves2bfloat162(h0, h1), hp1 = __halves2bfloat162(h2, h3);
        __nv_bfloat162 lp0 = __halves2bfloat162(l0, l1), lp1 = __halves2bfloat162(l2, l3);
        ((uint2*)g_Ah)[i] = make_uint2(*(unsigned*)&hp0, *(unsigned*)&hp1);
        ((uint2*)g_Al)[i] = make_uint2(*(unsigned*)&lp0, *(unsigned*)&lp1);
    }
}

// ------------- output GEMM via mma.sync bf16 (3-term split) -------------
// CTA 128(m: t of one batch) x 128(n: vocab), 8 warps (2x4), warp tile 64x32.
// K chunks of 64, 3-stage cp.async pipeline. Stage: Ah|Al|Bh|Bl 16KB each.
#define OST 65536
#define OAH 0
#define OAL 16384
#define OBH 32768
#define OBL 49152

__device__ __forceinline__ uint32_t osw(uint32_t r, uint32_t c8){
    return r * 128u + ((c8 ^ (r & 7u)) * 16u);
}

__global__ void __launch_bounds__(256, 1) k_out_mma(float* __restrict__ out,
                                                    const float* __restrict__ bout){
    extern __shared__ char osm[];
    __shared__ float bias[128];
    const uint32_t sb = smem_u32(osm);
    const int tid = threadIdx.x;
    const int wid = tid >> 5, lane = tid & 31;
    const int wm = wid >> 2, wn = wid & 3;           // warp grid 2x4
    const int m0 = blockIdx.x * 128;                 // batch = blockIdx.x
    const int n0 = blockIdx.y * 128;

    if (tid < 128) bias[tid] = bout[n0 + tid];

    // chunk loader: A needs 2048 x 16B (Ah+Al), B needs 2048 x 16B (Bh+Bl)
    auto load_chunk = [&](int st, int kc){
        const uint32_t stb = sb + (uint32_t)st * OST;
        #pragma unroll
        for (int q = 0; q < 8; q++){
            int i = tid + q * 256;                   // 0..2047: i<1024 -> Ah, else Al
            int r = (i & 1023) >> 3, c8 = i & 7;
            const __nv_bfloat16* src = (i < 1024) ? g_Ah : g_Al;
            uint32_t dst = stb + (i < 1024 ? OAH : OAL) + osw((uint32_t)r, (uint32_t)c8);
            CP_ASYNC16(dst, src + (size_t)(m0 + r) * 1024 + kc + c8 * 8);
        }
        #pragma unroll
        for (int q = 0; q < 8; q++){
            int i = tid + q * 256;                   // 0..2047: i<1024 -> Bh, else Bl
            int r = (i & 1023) >> 3, c8 = i & 7;
            const __nv_bfloat16* src = (i < 1024) ? g_Bh : g_Bl;
            uint32_t dst = stb + (i < 1024 ? OBH : OBL) + osw((uint32_t)r, (uint32_t)c8);
            CP_ASYNC16(dst, src + (size_t)(n0 + r) * 1024 + kc + c8 * 8);
        }
        CP_COMMIT();
    };

    float acc[4][4][4] = {};

    load_chunk(0, 0);
    load_chunk(1, 64);
    load_chunk(2, 128);

    #pragma unroll 1
    for (int c = 0; c < 16; c++){
        if      (c < 14) { CP_WAIT(2); }
        else if (c == 14){ CP_WAIT(1); }
        else             { CP_WAIT(0); }
        __syncthreads();

        const uint32_t base = sb + (uint32_t)(c % 3) * OST;
        #pragma unroll
        for (int ks = 0; ks < 4; ks++){
            const int k0 = ks * 16;
            uint32_t Ah[4][4], Al[4][4], Bh[4][2], Bl[4][2];
            {
                uint32_t arow = (uint32_t)(wm * 64 + ((lane >> 3) & 1) * 8 + (lane & 7));
                uint32_t ac8  = (uint32_t)((k0 >> 3) + (lane >> 4));
                #pragma unroll
                for (int f = 0; f < 4; f++){
                    uint32_t off = osw(arow + f * 16, ac8);
                    LDSM4(Ah[f], base + OAH + off);
                    LDSM4(Al[f], base + OAL + off);
                }
            }
            {
                uint32_t brow = (uint32_t)(wn * 32 + (lane & 7));
                uint32_t bc8  = (uint32_t)((k0 >> 3) + ((lane >> 3) & 1));
                #pragma unroll
                for (int g = 0; g < 4; g++){
                    uint32_t off = osw(brow + g * 8, bc8);
                    LDSM2(Bh[g], base + OBH + off);
                    LDSM2(Bl[g], base + OBL + off);
                }
            }
            #pragma unroll
            for (int f = 0; f < 4; f++)
                #pragma unroll
                for (int g = 0; g < 4; g++){
                    MMA_BF16(acc[f][g], Ah[f], Bh[g]);
                    MMA_BF16(acc[f][g], Al[f], Bh[g]);
                    MMA_BF16(acc[f][g], Ah[f], Bl[g]);
                }
        }
        __syncthreads();
        if (c + 3 < 16) load_chunk((c + 3) % 3, (c + 3) * 64);
    }

    // epilogue: out[b][v][t], t = m row
    const size_t ob = (size_t)blockIdx.x * VSZ * TDIM;
    #pragma unroll
    for (int f = 0; f < 4; f++){
        int m = wm * 64 + f * 16 + (lane >> 2);
        #pragma unroll
        for (int g = 0; g < 4; g++){
            int n = wn * 32 + g * 8 + (lane & 3) * 2;
            float* p = out + ob + (size_t)(n0 + n) * TDIM + m;
            p[0]        = acc[f][g][0] + bias[n];
            p[TDIM]     = acc[f][g][1] + bias[n + 1];
            p[8]        = acc[f][g][2] + bias[n];
            p[8 + TDIM] = acc[f][g][3] + bias[n + 1];
        }
    }
}

// ------------- launcher -------------
extern "C" void kernel_launch(void* const* d_in, const int* in_sizes, int n_in,
                              void* d_out, int out_size){
    const int*   tar  = (const int*)  d_in[0];
    const float* h    = (const float*)d_in[1];
    const float* s0   = (const float*)d_in[2];
    const float* c0   = (const float*)d_in[3];
    const float* emb  = (const float*)d_in[4];
    const float* Wih0 = (const float*)d_in[5];
    const float* Whh0 = (const float*)d_in[6];
    const float* bih0 = (const float*)d_in[7];
    const float* bhh0 = (const float*)d_in[8];
    const float* Wih1 = (const float*)d_in[9];
    const float* Whh1 = (const float*)d_in[10];
    const float* bih1 = (const float*)d_in[11];
    const float* bhh1 = (const float*)d_in[12];
    const float* Wout = (const float*)d_in[13];
    const float* bout = (const float*)d_in[14];
    float* out = (float*)d_out;

    static int attr_set = 0;
    if (!attr_set){
        cudaFuncSetAttribute(k_rec, cudaFuncAttributeMaxDynamicSharedMemorySize,
                             (int)sizeof(RecSmem));
        cudaFuncSetAttribute(k_out_mma, cudaFuncAttributeMaxDynamicSharedMemorySize,
                             3 * OST);
        attr_set = 1;
    }

    k_init<<<64, 256>>>(s0, c0);
    k_cvtW<<<2048, 256>>>(Wout);
    k_x0<<<dim3(32, 64), 256>>>(tar, emb, Wih0, bih0, bhh0);
    k_rec<<<NCTA, NTHR, sizeof(RecSmem)>>>(h, c0, Whh0, Wih1, Whh1, bih1, bhh1);
    k_cvtA<<<512, 256>>>();
    k_out_mma<<<dim3(32, 250), 256, 3 * OST>>>(out, bout);
}

// round 8
// speedup vs baseline: 4.7171x; 1.0379x over previous
#include <cuda_runtime.h>
#include <cuda_bf16.h>
#include <math.h>
#include <stdint.h>

#define VSZ  32000
#define EDIM 256
#define DDIM 512
#define BDIM 32
#define TDIM 128
#define SDIM 128
#define PADI 3
#define G4D  2048
#define NCTA 128
#define NTHR 256

// ------------- static device scratch -------------
__device__ float g_X0[(size_t)TDIM * BDIM * G4D];          // 33.5 MB
__device__ float g_A [(size_t)BDIM * TDIM * 2 * DDIM];     // 16.8 MB, row = b*T+t
__device__ float g_s0[2][BDIM * DDIM];
__device__ float g_s1[2][BDIM * DDIM];
__device__ unsigned g_bar_cnt = 0;
__device__ unsigned g_bar_gen = 0;

// bf16 split operands for the big GEMM
__device__ __nv_bfloat16 g_Ah[(size_t)4096 * 1024];
__device__ __nv_bfloat16 g_Al[(size_t)4096 * 1024];
__device__ __nv_bfloat16 g_Bh[(size_t)VSZ * 1024];
__device__ __nv_bfloat16 g_Bl[(size_t)VSZ * 1024];

__device__ __forceinline__ float sigf(float x){ return 1.0f / (1.0f + expf(-x)); }

__device__ __forceinline__ uint32_t smem_u32(const void* p){
    uint32_t a;
    asm("{ .reg .u64 t; cvta.to.shared.u64 t, %1; cvt.u32.u64 %0, t; }" : "=r"(a) : "l"(p));
    return a;
}

#define CP_ASYNC16(dst, src) \
    asm volatile("cp.async.cg.shared.global [%0], [%1], 16;" :: "r"(dst), "l"(src))
#define CP_COMMIT() asm volatile("cp.async.commit_group;" ::: "memory")
#define CP_WAIT(n)  asm volatile("cp.async.wait_group %0;" :: "n"(n) : "memory")

#define LDSM4(r, a) \
    asm volatile("ldmatrix.sync.aligned.m8n8.x4.shared.b16 {%0,%1,%2,%3}, [%4];" \
        : "=r"((r)[0]), "=r"((r)[1]), "=r"((r)[2]), "=r"((r)[3]) : "r"(a))
#define LDSM2(r, a) \
    asm volatile("ldmatrix.sync.aligned.m8n8.x2.shared.b16 {%0,%1}, [%2];" \
        : "=r"((r)[0]), "=r"((r)[1]) : "r"(a))
#define MMA_BF16(d, a, b) \
    asm volatile("mma.sync.aligned.m16n8k16.row.col.f32.bf16.bf16.f32 " \
        "{%0,%1,%2,%3}, {%4,%5,%6,%7}, {%8,%9}, {%0,%1,%2,%3};" \
        : "+f"((d)[0]), "+f"((d)[1]), "+f"((d)[2]), "+f"((d)[3]) \
        : "r"((a)[0]), "r"((a)[1]), "r"((a)[2]), "r"((a)[3]), "r"((b)[0]), "r"((b)[1]))

// ------------- init recurrent state -------------
__global__ void k_init(const float* __restrict__ s0, const float* __restrict__ c0){
    int i = blockIdx.x * 256 + threadIdx.x;
    if (i < BDIM * DDIM){
        g_s0[0][i] = s0[i];
        g_s1[0][i] = s0[BDIM * DDIM + i];
    }
}

// ------------- X0 = emb_eff[tok] @ Wih0^T + bih0 + bhh0 -------------
__global__ void k_x0(const int* __restrict__ tar, const float* __restrict__ emb,
                     const float* __restrict__ W, const float* __restrict__ b1,
                     const float* __restrict__ b2){
    __shared__ __align__(16) float Ast[32][68];
    __shared__ __align__(16) float Bst[32][68];
    const int tid = threadIdx.x;
    const int n0 = blockIdx.x * 64, m0 = blockIdx.y * 64;
    const int mg = tid >> 4, ng = tid & 15;
    const int ml0 = mg * 4, nl0 = ng * 4;
    const int kl = tid & 31, rl = tid >> 5;
    float acc[4][4] = {};
    for (int kc = 0; kc < EDIM; kc += 32){
        #pragma unroll
        for (int l = 0; l < 8; l++){
            int ml = rl + l * 8;
            int m  = m0 + ml;
            int tt = m >> 5, bb = m & 31;
            int tok = tar[bb * TDIM + tt];
            Ast[kl][ml] = (tok == PADI) ? 0.0f : emb[tok * EDIM + kc + kl];
            int nl = rl + l * 8;
            Bst[kl][nl] = W[(n0 + nl) * EDIM + kc + kl];
        }
        __syncthreads();
        #pragma unroll 8
        for (int k = 0; k < 32; k++){
            float ra[4], rb[4];
            #pragma unroll
            for (int i = 0; i < 4; i++) ra[i] = Ast[k][ml0 + i];
            #pragma unroll
            for (int j = 0; j < 4; j++) rb[j] = Bst[k][nl0 + j];
            #pragma unroll
            for (int i = 0; i < 4; i++)
                #pragma unroll
                for (int j = 0; j < 4; j++) acc[i][j] += ra[i] * rb[j];
        }
        __syncthreads();
    }
    #pragma unroll
    for (int i = 0; i < 4; i++){
        int m = m0 + ml0 + i;
        #pragma unroll
        for (int j = 0; j < 4; j++){
            int n = n0 + nl0 + j;
            g_X0[(size_t)m * G4D + n] = acc[i][j] + b1[n] + b2[n];
        }
    }
}

// ------------- persistent recurrence kernel v2 -------------
#define W0STR 129   // float4 row stride
#define W1STR 257   // float4 row stride
#define SCOL  33    // S4 row stride in float4

struct RecSmem {
    float4 W0[16 * W0STR];        // 33.0 KB
    float4 W1[16 * W1STR];        // 65.8 KB
    float4 S4[128 * SCOL];        // 67.6 KB  staged s vector [kq][col]
    float  gpart[8 * 16 * SCOL];  // 16.9 KB  per-warp partials
    float  csm0[128];
    float  csm1[128];
    float  bsum[16];
    float  s1s[512];
    float  sc[128];
    float  red[4];
    unsigned gen0;
};

__device__ __forceinline__ void gridbar(unsigned target){
    __syncthreads();
    if (threadIdx.x == 0){
        __threadfence();
        unsigned a = atomicAdd(&g_bar_cnt, 1u);
        if (a == NCTA - 1u){
            g_bar_cnt = 0u;
            __threadfence();
            atomicAdd(&g_bar_gen, 1u);
        } else {
            volatile unsigned* p = &g_bar_gen;
            while ((int)(*p - target) < 0) __nanosleep(32);
        }
        __threadfence();
    }
    __syncthreads();
}

// staging swizzle: column = (b + ((kq>>2)&6)) & 31  -> conflict-free STS + LDS
__device__ __forceinline__ int scol(int kq, int b){
    return (b + ((kq >> 2) & 6)) & 31;
}

__global__ void __launch_bounds__(NTHR, 1) k_rec(
    const float* __restrict__ h,   const float* __restrict__ c0in,
    const float* __restrict__ Whh0,
    const float* __restrict__ Wih1, const float* __restrict__ Whh1,
    const float* __restrict__ bih1, const float* __restrict__ bhh1)
{
    extern __shared__ RecSmem sm[];
    const int tid = threadIdx.x;
    const int d0  = blockIdx.x * 4;
    const int kw  = tid >> 5;       // warp id = k-slice owner (0..7)
    const int lane = tid & 31;
    const int rg = lane >> 3;       // rows rg, rg+4, rg+8, rg+12
    const int bg = lane & 7;        // batches bg, bg+8, bg+16, bg+24

    // ---- prologue ----
    if (tid == 0) sm->gen0 = *(volatile unsigned*)&g_bar_gen;
    for (int i = tid; i < 16 * 128; i += NTHR){
        int r_l = i >> 7, kq = i & 127;
        int gr  = (r_l >> 2) * DDIM + d0 + (r_l & 3);
        sm->W0[r_l * W0STR + kq] = *(const float4*)(Whh0 + (size_t)gr * DDIM + kq * 4);
    }
    for (int i = tid; i < 16 * 256; i += NTHR){
        int r_l = i >> 8, kq = i & 255;
        int gr  = (r_l >> 2) * DDIM + d0 + (r_l & 3);
        float4 v;
        if (kq < 128) v = *(const float4*)(Wih1 + (size_t)gr * DDIM + kq * 4);
        else          v = *(const float4*)(Whh1 + (size_t)gr * DDIM + (kq - 128) * 4);
        sm->W1[r_l * W1STR + kq] = v;
    }
    if (tid < 16){
        int gr = (tid >> 2) * DDIM + d0 + (tid & 3);
        sm->bsum[tid] = bih1[gr] + bhh1[gr];
    }
    if (tid < 128){
        int dl = tid >> 5, b = tid & 31;
        sm->csm0[tid] = c0in[b * DDIM + d0 + dl];
        sm->csm1[tid] = c0in[BDIM * DDIM + b * DDIM + d0 + dl];
    }
    __syncthreads();
    const unsigned gen0 = sm->gen0;

    for (int t = 0; t < TDIM; t++){
        const int ping = t & 1;

        // ================= cell0 =================
        {
            const float* Sg = g_s0[ping];
            for (int i = tid; i < 4096; i += NTHR){
                int b = i >> 7, kq = i & 127;
                sm->S4[kq * SCOL + scol(kq, b)] = ((const float4*)(Sg + b * DDIM))[kq];
            }
            __syncthreads();

            // prefetch X0 (consumed after compute)
            float x0v[4] = {0.f, 0.f, 0.f, 0.f};
            if (tid < 128){
                int dl = tid >> 5, b = tid & 31;
                const float* xp = g_X0 + ((size_t)t * BDIM + b) * G4D + d0 + dl;
                #pragma unroll
                for (int q = 0; q < 4; q++) x0v[q] = xp[q * DDIM];
            }

            float acc[4][4] = {};
            const float4* wbase = sm->W0 + rg * W0STR + kw * 16;
            #pragma unroll
            for (int kk = 0; kk < 16; kk++){
                const int kq = kw * 16 + kk;
                const int sh = (kq >> 2) & 6;
                float4 wv[4], sv[4];
                #pragma unroll
                for (int i = 0; i < 4; i++) wv[i] = wbase[i * 4 * W0STR + kk];
                const float4* srow = sm->S4 + kq * SCOL;
                #pragma unroll
                for (int j = 0; j < 4; j++) sv[j] = srow[(bg + j * 8 + sh) & 31];
                #pragma unroll
                for (int i = 0; i < 4; i++)
                    #pragma unroll
                    for (int j = 0; j < 4; j++)
                        acc[i][j] += wv[i].x * sv[j].x + wv[i].y * sv[j].y
                                   + wv[i].z * sv[j].z + wv[i].w * sv[j].w;
            }
            #pragma unroll
            for (int i = 0; i < 4; i++)
                #pragma unroll
                for (int j = 0; j < 4; j++)
                    sm->gpart[(kw * 16 + rg + 4 * i) * SCOL + bg + 8 * j] = acc[i][j];
            __syncthreads();

            if (tid < 128){
                int dl = tid >> 5, b = tid & 31;
                float gv[4];
                #pragma unroll
                for (int q = 0; q < 4; q++){
                    int r_l = q * 4 + dl;
                    float s = 0.f;
                    #pragma unroll
                    for (int w8 = 0; w8 < 8; w8++)
                        s += sm->gpart[(w8 * 16 + r_l) * SCOL + b];
                    gv[q] = s + x0v[q];
                }
                float cn = sigf(gv[1]) * sm->csm0[tid] + sigf(gv[0]) * tanhf(gv[2]);
                sm->csm0[tid] = cn;
                g_s0[ping ^ 1][b * DDIM + d0 + dl] = sigf(gv[3]) * tanhf(cn);
            }
        }
        gridbar(gen0 + 2 * t + 1);

        // ================= cell1 =================
        {
            float acc1[4][4] = {};
            #pragma unroll 1
            for (int c = 0; c < 2; c++){
                const float* Ss = c ? g_s1[ping] : g_s0[ping ^ 1];
                for (int i = tid; i < 4096; i += NTHR){
                    int b = i >> 7, kq = i & 127;
                    sm->S4[kq * SCOL + scol(kq, b)] = ((const float4*)(Ss + b * DDIM))[kq];
                }
                __syncthreads();

                const float4* wbase = sm->W1 + rg * W1STR + c * 128 + kw * 16;
                #pragma unroll
                for (int kk = 0; kk < 16; kk++){
                    const int kq = kw * 16 + kk;
                    const int sh = (kq >> 2) & 6;
                    float4 wv[4], sv[4];
                    #pragma unroll
                    for (int i = 0; i < 4; i++) wv[i] = wbase[i * 4 * W1STR + kk];
                    const float4* srow = sm->S4 + kq * SCOL;
                    #pragma unroll
                    for (int j = 0; j < 4; j++) sv[j] = srow[(bg + j * 8 + sh) & 31];
                    #pragma unroll
                    for (int i = 0; i < 4; i++)
                        #pragma unroll
                        for (int j = 0; j < 4; j++)
                            acc1[i][j] += wv[i].x * sv[j].x + wv[i].y * sv[j].y
                                        + wv[i].z * sv[j].z + wv[i].w * sv[j].w;
                }
                __syncthreads();
            }
            #pragma unroll
            for (int i = 0; i < 4; i++)
                #pragma unroll
                for (int j = 0; j < 4; j++)
                    sm->gpart[(kw * 16 + rg + 4 * i) * SCOL + bg + 8 * j] = acc1[i][j];
            __syncthreads();

            if (tid < 128){
                int dl = tid >> 5, b = tid & 31;
                float gv[4];
                #pragma unroll
                for (int q = 0; q < 4; q++){
                    int r_l = q * 4 + dl;
                    float s = 0.f;
                    #pragma unroll
                    for (int w8 = 0; w8 < 8; w8++)
                        s += sm->gpart[(w8 * 16 + r_l) * SCOL + b];
                    gv[q] = s + sm->bsum[r_l];
                }
                float cn = sigf(gv[1]) * sm->csm1[tid] + sigf(gv[0]) * tanhf(gv[2]);
                sm->csm1[tid] = cn;
                float sn = sigf(gv[3]) * tanhf(cn);
                g_s1[ping ^ 1][b * DDIM + d0 + dl] = sn;
                g_A[((size_t)b * TDIM + t) * (2 * DDIM) + d0 + dl] = sn;
            }
        }
        gridbar(gen0 + 2 * t + 2);

        // ================= attention (CTAs 0..31) =================
        if (blockIdx.x < BDIM){
            const int b = blockIdx.x;
            const float* s1n = g_s1[ping ^ 1] + b * DDIM;
            for (int i = tid; i < DDIM; i += NTHR) sm->s1s[i] = s1n[i];
            __syncthreads();
            const float* hb = h + (size_t)b * SDIM * DDIM;
            for (int so = 0; so < 16; so++){
                int s = kw * 16 + so;
                const float* hr = hb + (size_t)s * DDIM;
                float p = 0.0f;
                #pragma unroll
                for (int j2 = 0; j2 < 16; j2++) p += hr[lane + 32 * j2] * sm->s1s[lane + 32 * j2];
                #pragma unroll
                for (int off = 16; off; off >>= 1) p += __shfl_xor_sync(0xffffffffu, p, off);
                if (lane == 0) sm->sc[s] = p;
            }
            __syncthreads();
            if (tid < 128){
                float v = sm->sc[tid];
                float mx = v;
                #pragma unroll
                for (int off = 16; off; off >>= 1) mx = fmaxf(mx, __shfl_xor_sync(0xffffffffu, mx, off));
                if (lane == 0) sm->red[kw] = mx;
            }
            __syncthreads();
            if (tid < 128){
                float mx = fmaxf(fmaxf(sm->red[0], sm->red[1]), fmaxf(sm->red[2], sm->red[3]));
                float e = expf(sm->sc[tid] - mx);
                float smv = e;
                #pragma unroll
                for (int off = 16; off; off >>= 1) smv += __shfl_xor_sync(0xffffffffu, smv, off);
                __syncwarp();
                if (lane == 0) sm->red[kw] = smv;
                sm->s1s[tid] = e;
            }
            __syncthreads();
            if (tid < 128){
                float smv = sm->red[0] + sm->red[1] + sm->red[2] + sm->red[3];
                sm->sc[tid] = sm->s1s[tid] / smv;
            }
            __syncthreads();
            float2 accz = make_float2(0.f, 0.f);
            int d2 = tid * 2;
            #pragma unroll 4
            for (int s = 0; s < SDIM; s++){
                float a = sm->sc[s];
                float2 hv = *(const float2*)(hb + (size_t)s * DDIM + d2);
                accz.x += a * hv.x; accz.y += a * hv.y;
            }
            *(float2*)(g_A + ((size_t)b * TDIM + t) * (2 * DDIM) + DDIM + d2) = accz;
            __syncthreads();
        }
    }
}

// ------------- bf16 hi/lo split conversions -------------
__global__ void k_cvtW(const float* __restrict__ W){
    const size_t total = (size_t)VSZ * 1024 / 4;
    for (size_t i = (size_t)blockIdx.x * blockDim.x + threadIdx.x; i < total;
         i += (size_t)gridDim.x * blockDim.x){
        float4 v = ((const float4*)W)[i];
        __nv_bfloat16 h0 = __float2bfloat16(v.x), h1 = __float2bfloat16(v.y);
        __nv_bfloat16 h2 = __float2bfloat16(v.z), h3 = __float2bfloat16(v.w);
        __nv_bfloat16 l0 = __float2bfloat16(v.x - __bfloat162float(h0));
        __nv_bfloat16 l1 = __float2bfloat16(v.y - __bfloat162float(h1));
        __nv_bfloat16 l2 = __float2bfloat16(v.z - __bfloat162float(h2));
        __nv_bfloat16 l3 = __float2bfloat16(v.w - __bfloat162float(h3));
        __nv_bfloat162 hp0 = __halves2bfloat162(h0, h1), hp1 = __halves2bfloat162(h2, h3);
        __nv_bfloat162 lp0 = __halves2bfloat162(l0, l1), lp1 = __halves2bfloat162(l2, l3);
        ((uint2*)g_Bh)[i] = make_uint2(*(unsigned*)&hp0, *(unsigned*)&hp1);
        ((uint2*)g_Bl)[i] = make_uint2(*(unsigned*)&lp0, *(unsigned*)&lp1);
    }
}
__global__ void k_cvtA(void){
    const size_t total = (size_t)4096 * 1024 / 4;
    for (size_t i = (size_t)blockIdx.x * blockDim.x + threadIdx.x; i < total;
         i += (size_t)gridDim.x * blockDim.x){
        float4 v = ((const float4*)g_A)[i];
        __nv_bfloat16 h0 = __float2bfloat16(v.x), h1 = __float2bfloat16(v.y);
        __nv_bfloat16 h2 = __float2bfloat16(v.z), h3 = __float2bfloat16(v.w);
        __nv_bfloat16 l0 = __float2bfloat16(v.x - __bfloat162float(h0));
        __nv_bfloat16 l1 = __float2bfloat16(v.y - __bfloat162float(h1));
        __nv_bfloat16 l2 = __float2bfloat16(v.z - __bfloat162float(h2));
        __nv_bfloat16 l3 = __float2bfloat16(v.w - __bfloat162float(h3));
        __nv_bfloat162 hp0 = __halves2bfloat162(h0, h1), hp1 = __halves2bfloat162(h2, h3);
        __nv_bfloat162 lp0 = __halves2bfloat162(l0, l1), lp1 = __halves2bfloat162(l2, l3);
        ((uint2*)g_Ah)[i] = make_uint2(*(unsigned*)&hp0, *(unsigned*)&hp1);
        ((uint2*)g_Al)[i] = make_uint2(*(unsigned*)&lp0, *(unsigned*)&lp1);
    }
}

// ------------- output GEMM via mma.sync bf16 (3-term split) -------------
#define OST 65536
#define OAH 0
#define OAL 16384
#define OBH 32768
#define OBL 49152

__device__ __forceinline__ uint32_t osw(uint32_t r, uint32_t c8){
    return r * 128u + ((c8 ^ (r & 7u)) * 16u);
}

__global__ void __launch_bounds__(256, 1) k_out_mma(float* __restrict__ out,
                                                    const float* __restrict__ bout){
    extern __shared__ char osm[];
    __shared__ float bias[128];
    const uint32_t sb = smem_u32(osm);
    const int tid = threadIdx.x;
    const int wid = tid >> 5, lane = tid & 31;
    const int wm = wid >> 2, wn = wid & 3;
    const int m0 = blockIdx.x * 128;
    const int n0 = blockIdx.y * 128;

    if (tid < 128) bias[tid] = bout[n0 + tid];

    auto load_chunk = [&](int st, int kc){
        const uint32_t stb = sb + (uint32_t)st * OST;
        #pragma unroll
        for (int q = 0; q < 8; q++){
            int i = tid + q * 256;
            int r = (i & 1023) >> 3, c8 = i & 7;
            const __nv_bfloat16* src = (i < 1024) ? g_Ah : g_Al;
            uint32_t dst = stb + (i < 1024 ? OAH : OAL) + osw((uint32_t)r, (uint32_t)c8);
            CP_ASYNC16(dst, src + (size_t)(m0 + r) * 1024 + kc + c8 * 8);
        }
        #pragma unroll
        for (int q = 0; q < 8; q++){
            int i = tid + q * 256;
            int r = (i & 1023) >> 3, c8 = i & 7;
            const __nv_bfloat16* src = (i < 1024) ? g_Bh : g_Bl;
            uint32_t dst = stb + (i < 1024 ? OBH : OBL) + osw((uint32_t)r, (uint32_t)c8);
            CP_ASYNC16(dst, src + (size_t)(n0 + r) * 1024 + kc + c8 * 8);
        }
        CP_COMMIT();
    };

    float acc[4][4][4] = {};

    load_chunk(0, 0);
    load_chunk(1, 64);
    load_chunk(2, 128);

    #pragma unroll 1
    for (int c = 0; c < 16; c++){
        if      (c < 14) { CP_WAIT(2); }
        else if (c == 14){ CP_WAIT(1); }
        else             { CP_WAIT(0); }
        __syncthreads();

        const uint32_t base = sb + (uint32_t)(c % 3) * OST;
        #pragma unroll
        for (int ks = 0; ks < 4; ks++){
            const int k0 = ks * 16;
            uint32_t Ah[4][4], Al[4][4], Bh[4][2], Bl[4][2];
            {
                uint32_t arow = (uint32_t)(wm * 64 + ((lane >> 3) & 1) * 8 + (lane & 7));
                uint32_t ac8  = (uint32_t)((k0 >> 3) + (lane >> 4));
                #pragma unroll
                for (int f = 0; f < 4; f++){
                    uint32_t off = osw(arow + f * 16, ac8);
                    LDSM4(Ah[f], base + OAH + off);
                    LDSM4(Al[f], base + OAL + off);
                }
            }
            {
                uint32_t brow = (uint32_t)(wn * 32 + (lane & 7));
                uint32_t bc8  = (uint32_t)((k0 >> 3) + ((lane >> 3) & 1));
                #pragma unroll
                for (int g = 0; g < 4; g++){
                    uint32_t off = osw(brow + g * 8, bc8);
                    LDSM2(Bh[g], base + OBH + off);
                    LDSM2(Bl[g], base + OBL + off);
                }
            }
            #pragma unroll
            for (int f = 0; f < 4; f++)
                #pragma unroll
                for (int g = 0; g < 4; g++){
                    MMA_BF16(acc[f][g], Ah[f], Bh[g]);
                    MMA_BF16(acc[f][g], Al[f], Bh[g]);
                    MMA_BF16(acc[f][g], Ah[f], Bl[g]);
                }
        }
        __syncthreads();
        if (c + 3 < 16) load_chunk((c + 3) % 3, (c + 3) * 64);
    }

    const size_t ob = (size_t)blockIdx.x * VSZ * TDIM;
    #pragma unroll
    for (int f = 0; f < 4; f++){
        int m = wm * 64 + f * 16 + (lane >> 2);
        #pragma unroll
        for (int g = 0; g < 4; g++){
            int n = wn * 32 + g * 8 + (lane & 3) * 2;
            float* p = out + ob + (size_t)(n0 + n) * TDIM + m;
            p[0]        = acc[f][g][0] + bias[n];
            p[TDIM]     = acc[f][g][1] + bias[n + 1];
            p[8]        = acc[f][g][2] + bias[n];
            p[8 + TDIM] = acc[f][g][3] + bias[n + 1];
        }
    }
}

// ------------- launcher -------------
extern "C" void kernel_launch(void* const* d_in, const int* in_sizes, int n_in,
                              void* d_out, int out_size){
    const int*   tar  = (const int*)  d_in[0];
    const float* h    = (const float*)d_in[1];
    const float* s0   = (const float*)d_in[2];
    const float* c0   = (const float*)d_in[3];
    const float* emb  = (const float*)d_in[4];
    const float* Wih0 = (const float*)d_in[5];
    const float* Whh0 = (const float*)d_in[6];
    const float* bih0 = (const float*)d_in[7];
    const float* bhh0 = (const float*)d_in[8];
    const float* Wih1 = (const float*)d_in[9];
    const float* Whh1 = (const float*)d_in[10];
    const float* bih1 = (const float*)d_in[11];
    const float* bhh1 = (const float*)d_in[12];
    const float* Wout = (const float*)d_in[13];
    const float* bout = (const float*)d_in[14];
    float* out = (float*)d_out;

    static int attr_set = 0;
    if (!attr_set){
        cudaFuncSetAttribute(k_rec, cudaFuncAttributeMaxDynamicSharedMemorySize,
                             (int)sizeof(RecSmem));
        cudaFuncSetAttribute(k_out_mma, cudaFuncAttributeMaxDynamicSharedMemorySize,
                             3 * OST);
        attr_set = 1;
    }

    k_init<<<64, 256>>>(s0, c0);
    k_cvtW<<<2048, 256>>>(Wout);
    k_x0<<<dim3(32, 64), 256>>>(tar, emb, Wih0, bih0, bhh0);
    k_rec<<<NCTA, NTHR, sizeof(RecSmem)>>>(h, c0, Whh0, Wih1, Whh1, bih1, bhh1);
    k_cvtA<<<512, 256>>>();
    k_out_mma<<<dim3(32, 250), 256, 3 * OST>>>(out, bout);
}

// round 9
// speedup vs baseline: 6.4832x; 1.3744x over previous
#include <cuda_runtime.h>
#include <cuda_bf16.h>
#include <math.h>
#include <stdint.h>

#define VSZ  32000
#define EDIM 256
#define DDIM 512
#define BDIM 32
#define TDIM 128
#define SDIM 128
#define PADI 3
#define G4D  2048
#define NCTA 128
#define NTHR 256

// ------------- static device scratch -------------
__device__ float g_X0[(size_t)TDIM * BDIM * G4D];          // 33.5 MB
__device__ float g_A [(size_t)BDIM * TDIM * 2 * DDIM];     // s1 half only used now
__device__ float g_s0[2][BDIM * DDIM];
__device__ float g_s1[2][BDIM * DDIM];
__device__ unsigned g_bar_cnt = 0;
__device__ unsigned g_bar_gen = 0;

// bf16 split operands for the big GEMM
__device__ __nv_bfloat16 g_Ah[(size_t)4096 * 1024];
__device__ __nv_bfloat16 g_Al[(size_t)4096 * 1024];
__device__ __nv_bfloat16 g_Bh[(size_t)VSZ * 1024];
__device__ __nv_bfloat16 g_Bl[(size_t)VSZ * 1024];

__device__ __forceinline__ float sigf(float x){ return 1.0f / (1.0f + expf(-x)); }

__device__ __forceinline__ uint32_t smem_u32(const void* p){
    uint32_t a;
    asm("{ .reg .u64 t; cvta.to.shared.u64 t, %1; cvt.u32.u64 %0, t; }" : "=r"(a) : "l"(p));
    return a;
}

#define CP_ASYNC16(dst, src) \
    asm volatile("cp.async.cg.shared.global [%0], [%1], 16;" :: "r"(dst), "l"(src))
#define CP_COMMIT() asm volatile("cp.async.commit_group;" ::: "memory")
#define CP_WAIT(n)  asm volatile("cp.async.wait_group %0;" :: "n"(n) : "memory")

#define LDSM4(r, a) \
    asm volatile("ldmatrix.sync.aligned.m8n8.x4.shared.b16 {%0,%1,%2,%3}, [%4];" \
        : "=r"((r)[0]), "=r"((r)[1]), "=r"((r)[2]), "=r"((r)[3]) : "r"(a))
#define LDSM2(r, a) \
    asm volatile("ldmatrix.sync.aligned.m8n8.x2.shared.b16 {%0,%1}, [%2];" \
        : "=r"((r)[0]), "=r"((r)[1]) : "r"(a))
#define MMA_BF16(d, a, b) \
    asm volatile("mma.sync.aligned.m16n8k16.row.col.f32.bf16.bf16.f32 " \
        "{%0,%1,%2,%3}, {%4,%5,%6,%7}, {%8,%9}, {%0,%1,%2,%3};" \
        : "+f"((d)[0]), "+f"((d)[1]), "+f"((d)[2]), "+f"((d)[3]) \
        : "r"((a)[0]), "r"((a)[1]), "r"((a)[2]), "r"((a)[3]), "r"((b)[0]), "r"((b)[1]))

// split helpers
__device__ __forceinline__ void split2(float x, float y, unsigned& hi, unsigned& lo){
    __nv_bfloat16 hx = __float2bfloat16(x), hy = __float2bfloat16(y);
    __nv_bfloat16 lx = __float2bfloat16(x - __bfloat162float(hx));
    __nv_bfloat16 ly = __float2bfloat16(y - __bfloat162float(hy));
    __nv_bfloat162 hp = __halves2bfloat162(hx, hy), lp = __halves2bfloat162(lx, ly);
    hi = *(unsigned*)&hp; lo = *(unsigned*)&lp;
}

// ------------- init recurrent state -------------
__global__ void k_init(const float* __restrict__ s0, const float* __restrict__ c0){
    int i = blockIdx.x * 256 + threadIdx.x;
    if (i < BDIM * DDIM){
        g_s0[0][i] = s0[i];
        g_s1[0][i] = s0[BDIM * DDIM + i];
    }
}

// ------------- X0 = emb_eff[tok] @ Wih0^T + bih0 + bhh0 -------------
__global__ void k_x0(const int* __restrict__ tar, const float* __restrict__ emb,
                     const float* __restrict__ W, const float* __restrict__ b1,
                     const float* __restrict__ b2){
    __shared__ __align__(16) float Ast[32][68];
    __shared__ __align__(16) float Bst[32][68];
    const int tid = threadIdx.x;
    const int n0 = blockIdx.x * 64, m0 = blockIdx.y * 64;
    const int mg = tid >> 4, ng = tid & 15;
    const int ml0 = mg * 4, nl0 = ng * 4;
    const int kl = tid & 31, rl = tid >> 5;
    float acc[4][4] = {};
    for (int kc = 0; kc < EDIM; kc += 32){
        #pragma unroll
        for (int l = 0; l < 8; l++){
            int ml = rl + l * 8;
            int m  = m0 + ml;
            int tt = m >> 5, bb = m & 31;
            int tok = tar[bb * TDIM + tt];
            Ast[kl][ml] = (tok == PADI) ? 0.0f : emb[tok * EDIM + kc + kl];
            int nl = rl + l * 8;
            Bst[kl][nl] = W[(n0 + nl) * EDIM + kc + kl];
        }
        __syncthreads();
        #pragma unroll 8
        for (int k = 0; k < 32; k++){
            float ra[4], rb[4];
            #pragma unroll
            for (int i = 0; i < 4; i++) ra[i] = Ast[k][ml0 + i];
            #pragma unroll
            for (int j = 0; j < 4; j++) rb[j] = Bst[k][nl0 + j];
            #pragma unroll
            for (int i = 0; i < 4; i++)
                #pragma unroll
                for (int j = 0; j < 4; j++) acc[i][j] += ra[i] * rb[j];
        }
        __syncthreads();
    }
    #pragma unroll
    for (int i = 0; i < 4; i++){
        int m = m0 + ml0 + i;
        #pragma unroll
        for (int j = 0; j < 4; j++){
            int n = n0 + nl0 + j;
            g_X0[(size_t)m * G4D + n] = acc[i][j] + b1[n] + b2[n];
        }
    }
}

// ------------- persistent recurrence kernel (cells only, no attention) -------------
#define W0STR 129
#define W1STR 257
#define SCOL  33

struct RecSmem {
    float4 W0[16 * W0STR];
    float4 W1[16 * W1STR];
    float4 S4[128 * SCOL];
    float  gpart[8 * 16 * SCOL];
    float  csm0[128];
    float  csm1[128];
    float  bsum[16];
    unsigned gen0;
};

__device__ __forceinline__ void gridbar(unsigned target){
    __syncthreads();
    if (threadIdx.x == 0){
        __threadfence();
        unsigned a = atomicAdd(&g_bar_cnt, 1u);
        if (a == NCTA - 1u){
            g_bar_cnt = 0u;
            __threadfence();
            atomicAdd(&g_bar_gen, 1u);
        } else {
            volatile unsigned* p = &g_bar_gen;
            while ((int)(*p - target) < 0) __nanosleep(32);
        }
        __threadfence();
    }
    __syncthreads();
}

__device__ __forceinline__ int scol(int kq, int b){
    return (b + ((kq >> 2) & 6)) & 31;
}

__global__ void __launch_bounds__(NTHR, 1) k_rec(
    const float* __restrict__ c0in,
    const float* __restrict__ Whh0,
    const float* __restrict__ Wih1, const float* __restrict__ Whh1,
    const float* __restrict__ bih1, const float* __restrict__ bhh1)
{
    extern __shared__ RecSmem sm[];
    const int tid = threadIdx.x;
    const int d0  = blockIdx.x * 4;
    const int kw  = tid >> 5;
    const int lane = tid & 31;
    const int rg = lane >> 3;
    const int bg = lane & 7;

    if (tid == 0) sm->gen0 = *(volatile unsigned*)&g_bar_gen;
    for (int i = tid; i < 16 * 128; i += NTHR){
        int r_l = i >> 7, kq = i & 127;
        int gr  = (r_l >> 2) * DDIM + d0 + (r_l & 3);
        sm->W0[r_l * W0STR + kq] = *(const float4*)(Whh0 + (size_t)gr * DDIM + kq * 4);
    }
    for (int i = tid; i < 16 * 256; i += NTHR){
        int r_l = i >> 8, kq = i & 255;
        int gr  = (r_l >> 2) * DDIM + d0 + (r_l & 3);
        float4 v;
        if (kq < 128) v = *(const float4*)(Wih1 + (size_t)gr * DDIM + kq * 4);
        else          v = *(const float4*)(Whh1 + (size_t)gr * DDIM + (kq - 128) * 4);
        sm->W1[r_l * W1STR + kq] = v;
    }
    if (tid < 16){
        int gr = (tid >> 2) * DDIM + d0 + (tid & 3);
        sm->bsum[tid] = bih1[gr] + bhh1[gr];
    }
    if (tid < 128){
        int dl = tid >> 5, b = tid & 31;
        sm->csm0[tid] = c0in[b * DDIM + d0 + dl];
        sm->csm1[tid] = c0in[BDIM * DDIM + b * DDIM + d0 + dl];
    }
    __syncthreads();
    const unsigned gen0 = sm->gen0;

    for (int t = 0; t < TDIM; t++){
        const int ping = t & 1;

        // ================= cell0 =================
        {
            const float* Sg = g_s0[ping];
            for (int i = tid; i < 4096; i += NTHR){
                int b = i >> 7, kq = i & 127;
                sm->S4[kq * SCOL + scol(kq, b)] = ((const float4*)(Sg + b * DDIM))[kq];
            }
            __syncthreads();

            float x0v[4] = {0.f, 0.f, 0.f, 0.f};
            if (tid < 128){
                int dl = tid >> 5, b = tid & 31;
                const float* xp = g_X0 + ((size_t)t * BDIM + b) * G4D + d0 + dl;
                #pragma unroll
                for (int q = 0; q < 4; q++) x0v[q] = xp[q * DDIM];
            }

            float acc[4][4] = {};
            const float4* wbase = sm->W0 + rg * W0STR + kw * 16;
            #pragma unroll
            for (int kk = 0; kk < 16; kk++){
                const int kq = kw * 16 + kk;
                const int sh = (kq >> 2) & 6;
                float4 wv[4], sv[4];
                #pragma unroll
                for (int i = 0; i < 4; i++) wv[i] = wbase[i * 4 * W0STR + kk];
                const float4* srow = sm->S4 + kq * SCOL;
                #pragma unroll
                for (int j = 0; j < 4; j++) sv[j] = srow[(bg + j * 8 + sh) & 31];
                #pragma unroll
                for (int i = 0; i < 4; i++)
                    #pragma unroll
                    for (int j = 0; j < 4; j++)
                        acc[i][j] += wv[i].x * sv[j].x + wv[i].y * sv[j].y
                                   + wv[i].z * sv[j].z + wv[i].w * sv[j].w;
            }
            #pragma unroll
            for (int i = 0; i < 4; i++)
                #pragma unroll
                for (int j = 0; j < 4; j++)
                    sm->gpart[(kw * 16 + rg + 4 * i) * SCOL + bg + 8 * j] = acc[i][j];
            __syncthreads();

            if (tid < 128){
                int dl = tid >> 5, b = tid & 31;
                float gv[4];
                #pragma unroll
                for (int q = 0; q < 4; q++){
                    int r_l = q * 4 + dl;
                    float s = 0.f;
                    #pragma unroll
                    for (int w8 = 0; w8 < 8; w8++)
                        s += sm->gpart[(w8 * 16 + r_l) * SCOL + b];
                    gv[q] = s + x0v[q];
                }
                float cn = sigf(gv[1]) * sm->csm0[tid] + sigf(gv[0]) * tanhf(gv[2]);
                sm->csm0[tid] = cn;
                g_s0[ping ^ 1][b * DDIM + d0 + dl] = sigf(gv[3]) * tanhf(cn);
            }
        }
        gridbar(gen0 + 2 * t + 1);

        // ================= cell1 =================
        {
            float acc1[4][4] = {};
            #pragma unroll 1
            for (int c = 0; c < 2; c++){
                const float* Ss = c ? g_s1[ping] : g_s0[ping ^ 1];
                for (int i = tid; i < 4096; i += NTHR){
                    int b = i >> 7, kq = i & 127;
                    sm->S4[kq * SCOL + scol(kq, b)] = ((const float4*)(Ss + b * DDIM))[kq];
                }
                __syncthreads();

                const float4* wbase = sm->W1 + rg * W1STR + c * 128 + kw * 16;
                #pragma unroll
                for (int kk = 0; kk < 16; kk++){
                    const int kq = kw * 16 + kk;
                    const int sh = (kq >> 2) & 6;
                    float4 wv[4], sv[4];
                    #pragma unroll
                    for (int i = 0; i < 4; i++) wv[i] = wbase[i * 4 * W1STR + kk];
                    const float4* srow = sm->S4 + kq * SCOL;
                    #pragma unroll
                    for (int j = 0; j < 4; j++) sv[j] = srow[(bg + j * 8 + sh) & 31];
                    #pragma unroll
                    for (int i = 0; i < 4; i++)
                        #pragma unroll
                        for (int j = 0; j < 4; j++)
                            acc1[i][j] += wv[i].x * sv[j].x + wv[i].y * sv[j].y
                                        + wv[i].z * sv[j].z + wv[i].w * sv[j].w;
                }
                __syncthreads();
            }
            #pragma unroll
            for (int i = 0; i < 4; i++)
                #pragma unroll
                for (int j = 0; j < 4; j++)
                    sm->gpart[(kw * 16 + rg + 4 * i) * SCOL + bg + 8 * j] = acc1[i][j];
            __syncthreads();

            if (tid < 128){
                int dl = tid >> 5, b = tid & 31;
                float gv[4];
                #pragma unroll
                for (int q = 0; q < 4; q++){
                    int r_l = q * 4 + dl;
                    float s = 0.f;
                    #pragma unroll
                    for (int w8 = 0; w8 < 8; w8++)
                        s += sm->gpart[(w8 * 16 + r_l) * SCOL + b];
                    gv[q] = s + sm->bsum[r_l];
                }
                float cn = sigf(gv[1]) * sm->csm1[tid] + sigf(gv[0]) * tanhf(gv[2]);
                sm->csm1[tid] = cn;
                float sn = sigf(gv[3]) * tanhf(cn);
                g_s1[ping ^ 1][b * DDIM + d0 + dl] = sn;
                g_A[((size_t)b * TDIM + t) * (2 * DDIM) + d0 + dl] = sn;
            }
        }
        gridbar(gen0 + 2 * t + 2);
    }
}

// ------------- parallel attention + direct bf16-split write -------------
// grid (16, 32): blockIdx.y = b, blockIdx.x = block of 8 t. 256 threads.
__global__ void __launch_bounds__(256) k_attn2(const float* __restrict__ h){
    __shared__ __align__(16) float s1s[8][516];
    __shared__ float sc[8][132];
    const int b = blockIdx.y, t0 = blockIdx.x * 8;
    const int tid = threadIdx.x, w = tid >> 5, lane = tid & 31;
    const size_t arow0 = ((size_t)b * TDIM + t0) * 1024;

    // stage s1 rows
    for (int i = tid; i < 1024; i += 256){
        int tt = i >> 7, q = i & 127;
        *(float4*)&s1s[tt][q * 4] = *(const float4*)(g_A + arow0 + (size_t)tt * 1024 + q * 4);
    }
    __syncthreads();

    const float* hb = h + (size_t)b * SDIM * DDIM;

    // scores: warp w handles s = w*16 .. w*16+15
    for (int j = 0; j < 16; j++){
        int s = w * 16 + j;
        const float4* hr = (const float4*)(hb + (size_t)s * DDIM);
        float4 hv[4];
        #pragma unroll
        for (int q = 0; q < 4; q++) hv[q] = hr[lane + 32 * q];
        float p[8];
        #pragma unroll
        for (int tt = 0; tt < 8; tt++){
            float acc = 0.f;
            #pragma unroll
            for (int q = 0; q < 4; q++){
                float4 sv = *(const float4*)&s1s[tt][(lane + 32 * q) * 4];
                acc += hv[q].x * sv.x + hv[q].y * sv.y + hv[q].z * sv.z + hv[q].w * sv.w;
            }
            p[tt] = acc;
        }
        #pragma unroll
        for (int tt = 0; tt < 8; tt++){
            #pragma unroll
            for (int off = 16; off; off >>= 1)
                p[tt] += __shfl_xor_sync(0xffffffffu, p[tt], off);
        }
        #pragma unroll
        for (int tt = 0; tt < 8; tt++)
            if (lane == tt) sc[tt][s] = p[tt];
    }
    __syncthreads();

    // softmax: warp w handles tt = w
    {
        float x[4];
        #pragma unroll
        for (int q = 0; q < 4; q++) x[q] = sc[w][lane + 32 * q];
        float mx = fmaxf(fmaxf(x[0], x[1]), fmaxf(x[2], x[3]));
        #pragma unroll
        for (int off = 16; off; off >>= 1) mx = fmaxf(mx, __shfl_xor_sync(0xffffffffu, mx, off));
        float e[4], sum = 0.f;
        #pragma unroll
        for (int q = 0; q < 4; q++){ e[q] = expf(x[q] - mx); sum += e[q]; }
        #pragma unroll
        for (int off = 16; off; off >>= 1) sum += __shfl_xor_sync(0xffffffffu, sum, off);
        float inv = 1.0f / sum;
        #pragma unroll
        for (int q = 0; q < 4; q++) sc[w][lane + 32 * q] = e[q] * inv;
    }
    __syncthreads();

    // z: thread owns d-pair d2 = tid*2 ; accumulate for all 8 t
    float az[8][2] = {};
    const int d2 = tid * 2;
    #pragma unroll 4
    for (int s = 0; s < SDIM; s++){
        float2 hv = *(const float2*)(hb + (size_t)s * DDIM + d2);
        #pragma unroll
        for (int tt = 0; tt < 8; tt++){
            float a = sc[tt][s];
            az[tt][0] += a * hv.x;
            az[tt][1] += a * hv.y;
        }
    }
    // write z splits (cols 512 + d2, d2+1)
    #pragma unroll
    for (int tt = 0; tt < 8; tt++){
        unsigned hi, lo;
        split2(az[tt][0], az[tt][1], hi, lo);
        size_t off = arow0 + (size_t)tt * 1024 + 512 + d2;
        *(unsigned*)(g_Ah + off) = hi;
        *(unsigned*)(g_Al + off) = lo;
    }
    // convert s1 half from smem (cols 0..511)
    for (int i = tid; i < 2048; i += 256){
        int tt = i >> 8, q = i & 255;            // q indexes pairs of floats
        float x = s1s[tt][q * 2], y = s1s[tt][q * 2 + 1];
        unsigned hi, lo;
        split2(x, y, hi, lo);
        size_t off = arow0 + (size_t)tt * 1024 + q * 2;
        *(unsigned*)(g_Ah + off) = hi;
        *(unsigned*)(g_Al + off) = lo;
    }
}

// ------------- bf16 hi/lo split of Wout -------------
__global__ void k_cvtW(const float* __restrict__ W){
    const size_t total = (size_t)VSZ * 1024 / 4;
    for (size_t i = (size_t)blockIdx.x * blockDim.x + threadIdx.x; i < total;
         i += (size_t)gridDim.x * blockDim.x){
        float4 v = ((const float4*)W)[i];
        unsigned h0, l0, h1, l1;
        split2(v.x, v.y, h0, l0);
        split2(v.z, v.w, h1, l1);
        ((uint2*)g_Bh)[i] = make_uint2(h0, h1);
        ((uint2*)g_Bl)[i] = make_uint2(l0, l1);
    }
}

// ------------- output GEMM via mma.sync bf16 (3-term split) -------------
#define OST 65536
#define OAH 0
#define OAL 16384
#define OBH 32768
#define OBL 49152

__device__ __forceinline__ uint32_t osw(uint32_t r, uint32_t c8){
    return r * 128u + ((c8 ^ (r & 7u)) * 16u);
}

__global__ void __launch_bounds__(256, 1) k_out_mma(float* __restrict__ out,
                                                    const float* __restrict__ bout){
    extern __shared__ char osm[];
    __shared__ float bias[128];
    const uint32_t sb = smem_u32(osm);
    const int tid = threadIdx.x;
    const int wid = tid >> 5, lane = tid & 31;
    const int wm = wid >> 2, wn = wid & 3;
    const int m0 = blockIdx.x * 128;
    const int n0 = blockIdx.y * 128;

    if (tid < 128) bias[tid] = bout[n0 + tid];

    auto load_chunk = [&](int st, int kc){
        const uint32_t stb = sb + (uint32_t)st * OST;
        #pragma unroll
        for (int q = 0; q < 8; q++){
            int i = tid + q * 256;
            int r = (i & 1023) >> 3, c8 = i & 7;
            const __nv_bfloat16* src = (i < 1024) ? g_Ah : g_Al;
            uint32_t dst = stb + (i < 1024 ? OAH : OAL) + osw((uint32_t)r, (uint32_t)c8);
            CP_ASYNC16(dst, src + (size_t)(m0 + r) * 1024 + kc + c8 * 8);
        }
        #pragma unroll
        for (int q = 0; q < 8; q++){
            int i = tid + q * 256;
            int r = (i & 1023) >> 3, c8 = i & 7;
            const __nv_bfloat16* src = (i < 1024) ? g_Bh : g_Bl;
            uint32_t dst = stb + (i < 1024 ? OBH : OBL) + osw((uint32_t)r, (uint32_t)c8);
            CP_ASYNC16(dst, src + (size_t)(n0 + r) * 1024 + kc + c8 * 8);
        }
        CP_COMMIT();
    };

    float acc[4][4][4] = {};

    load_chunk(0, 0);
    load_chunk(1, 64);
    load_chunk(2, 128);

    #pragma unroll 1
    for (int c = 0; c < 16; c++){
        if      (c < 14) { CP_WAIT(2); }
        else if (c == 14){ CP_WAIT(1); }
        else             { CP_WAIT(0); }
        __syncthreads();

        const uint32_t base = sb + (uint32_t)(c % 3) * OST;
        #pragma unroll
        for (int ks = 0; ks < 4; ks++){
            const int k0 = ks * 16;
            uint32_t Ah[4][4], Al[4][4], Bh[4][2], Bl[4][2];
            {
                uint32_t arow = (uint32_t)(wm * 64 + ((lane >> 3) & 1) * 8 + (lane & 7));
                uint32_t ac8  = (uint32_t)((k0 >> 3) + (lane >> 4));
                #pragma unroll
                for (int f = 0; f < 4; f++){
                    uint32_t off = osw(arow + f * 16, ac8);
                    LDSM4(Ah[f], base + OAH + off);
                    LDSM4(Al[f], base + OAL + off);
                }
            }
            {
                uint32_t brow = (uint32_t)(wn * 32 + (lane & 7));
                uint32_t bc8  = (uint32_t)((k0 >> 3) + ((lane >> 3) & 1));
                #pragma unroll
                for (int g = 0; g < 4; g++){
                    uint32_t off = osw(brow + g * 8, bc8);
                    LDSM2(Bh[g], base + OBH + off);
                    LDSM2(Bl[g], base + OBL + off);
                }
            }
            #pragma unroll
            for (int f = 0; f < 4; f++)
                #pragma unroll
                for (int g = 0; g < 4; g++){
                    MMA_BF16(acc[f][g], Ah[f], Bh[g]);
                    MMA_BF16(acc[f][g], Al[f], Bh[g]);
                    MMA_BF16(acc[f][g], Ah[f], Bl[g]);
                }
        }
        __syncthreads();
        if (c + 3 < 16) load_chunk((c + 3) % 3, (c + 3) * 64);
    }

    const size_t ob = (size_t)blockIdx.x * VSZ * TDIM;
    #pragma unroll
    for (int f = 0; f < 4; f++){
        int m = wm * 64 + f * 16 + (lane >> 2);
        #pragma unroll
        for (int g = 0; g < 4; g++){
            int n = wn * 32 + g * 8 + (lane & 3) * 2;
            float* p = out + ob + (size_t)(n0 + n) * TDIM + m;
            p[0]        = acc[f][g][0] + bias[n];
            p[TDIM]     = acc[f][g][1] + bias[n + 1];
            p[8]        = acc[f][g][2] + bias[n];
            p[8 + TDIM] = acc[f][g][3] + bias[n + 1];
        }
    }
}

// ------------- launcher -------------
extern "C" void kernel_launch(void* const* d_in, const int* in_sizes, int n_in,
                              void* d_out, int out_size){
    const int*   tar  = (const int*)  d_in[0];
    const float* h    = (const float*)d_in[1];
    const float* s0   = (const float*)d_in[2];
    const float* c0   = (const float*)d_in[3];
    const float* emb  = (const float*)d_in[4];
    const float* Wih0 = (const float*)d_in[5];
    const float* Whh0 = (const float*)d_in[6];
    const float* bih0 = (const float*)d_in[7];
    const float* bhh0 = (const float*)d_in[8];
    const float* Wih1 = (const float*)d_in[9];
    const float* Whh1 = (const float*)d_in[10];
    const float* bih1 = (const float*)d_in[11];
    const float* bhh1 = (const float*)d_in[12];
    const float* Wout = (const float*)d_in[13];
    const float* bout = (const float*)d_in[14];
    float* out = (float*)d_out;

    static int attr_set = 0;
    if (!attr_set){
        cudaFuncSetAttribute(k_rec, cudaFuncAttributeMaxDynamicSharedMemorySize,
                             (int)sizeof(RecSmem));
        cudaFuncSetAttribute(k_out_mma, cudaFuncAttributeMaxDynamicSharedMemorySize,
                             3 * OST);
        attr_set = 1;
    }

    k_init<<<64, 256>>>(s0, c0);
    k_cvtW<<<2048, 256>>>(Wout);
    k_x0<<<dim3(32, 64), 256>>>(tar, emb, Wih0, bih0, bhh0);
    k_rec<<<NCTA, NTHR, sizeof(RecSmem)>>>(c0, Whh0, Wih1, Whh1, bih1, bhh1);
    k_attn2<<<dim3(16, 32), 256>>>(h);
    k_out_mma<<<dim3(32, 250), 256, 3 * OST>>>(out, bout);
}